// round 9
// baseline (speedup 1.0000x reference)
#include <cuda_runtime.h>

#define NN 100000
#define NE 1600000
#define HD 64
#define BN_EPS 1e-5f
#define NCHUNKS 25   // ceil(NN/4096)

// ---------------- scratch (device globals; no runtime allocation) ----------
static __device__ __align__(16) float g_h[NN * HD];   // running node features
static __device__ __align__(16) float g_z[NN * HD];   // h + aggregation
static __device__ __align__(16) float g_y[NN * HD];   // MLP output (pre-BN)
static __device__ int    g_srcs[NE];                  // src sorted by dst (CSR)
static __device__ float4 g_ef[NE];                    // edge features sorted by dst
static __device__ int    g_deg[NN];                   // zero at entry (invariant)
static __device__ int    g_wcur[NN];                  // zero at entry (invariant)
static __device__ int    g_rowloc[NN];                // chunk-local prefix
static __device__ int    g_rowptr[NN + 1];            // final CSR rowptr
static __device__ int    g_part[32];                  // per-chunk edge totals
static __device__ float  g_stats[2 * HD];             // per-channel sum / sumsq

typedef unsigned long long u64;

__device__ __forceinline__ u64 pk2(float x, float y) {
    u64 r; asm("mov.b64 %0,{%1,%2};" : "=l"(r) : "f"(x), "f"(y)); return r;
}
__device__ __forceinline__ float2 upk2(u64 a) {
    float2 r; asm("mov.b64 {%0,%1},%2;" : "=f"(r.x), "=f"(r.y) : "l"(a)); return r;
}
__device__ __forceinline__ u64 ffma2(u64 a, u64 b, u64 c) {
    u64 d; asm("fma.rn.f32x2 %0,%1,%2,%3;" : "=l"(d) : "l"(a), "l"(b), "l"(c)); return d;
}

// ---------------- preprocessing (3 launches) --------------------------------

__global__ void k_hist(const int* __restrict__ dst) {
    int i = blockIdx.x * blockDim.x + threadIdx.x;
    if (i < NE) atomicAdd(&g_deg[dst[i]], 1);
}

__global__ void __launch_bounds__(512, 1) k_scan1() {
    __shared__ int s[512];
    int tid = threadIdx.x;
    int base = blockIdx.x * 4096 + tid * 8;
    int items[8]; int t = 0;
#pragma unroll
    for (int j = 0; j < 8; ++j) {
        int idx = base + j;
        int v = 0;
        if (idx < NN) { v = g_deg[idx]; g_deg[idx] = 0; g_wcur[idx] = 0; }
        items[j] = v; t += v;
    }
    s[tid] = t;
    __syncthreads();
    for (int off = 1; off < 512; off <<= 1) {
        int x = (tid >= off) ? s[tid - off] : 0;
        __syncthreads();
        s[tid] += x;
        __syncthreads();
    }
    int run = s[tid] - t;
#pragma unroll
    for (int j = 0; j < 8; ++j) {
        int idx = base + j;
        if (idx < NN) g_rowloc[idx] = run;
        run += items[j];
    }
    if (tid == 511) g_part[blockIdx.x] = s[511];
}

__global__ void k_scatter(const int* __restrict__ src, const int* __restrict__ dst,
                          const float4* __restrict__ ef, const float4* __restrict__ nf) {
    __shared__ int s_off[32];
    if (threadIdx.x < 32) {
        int orig = (threadIdx.x < NCHUNKS) ? g_part[threadIdx.x] : 0;
        int v = orig;
        for (int off = 1; off < 32; off <<= 1) {
            int x = __shfl_up_sync(0xffffffffu, v, off);
            if ((threadIdx.x & 31) >= off) v += x;
        }
        s_off[threadIdx.x] = v - orig;  // exclusive prefix
    }
    __syncthreads();
    int gt = blockIdx.x * blockDim.x + threadIdx.x;
    int gsz = gridDim.x * blockDim.x;
    for (int i = gt; i < NE; i += gsz) {
        int d = dst[i];
        int pos = g_rowloc[d] + s_off[d >> 12] + atomicAdd(&g_wcur[d], 1);
        g_srcs[pos] = src[i];
        g_ef[pos]   = ef[i];
    }
    for (int i = gt; i < NN; i += gsz)
        g_rowptr[i] = g_rowloc[i] + s_off[i >> 12];
    if (gt == 0) g_rowptr[NN] = NE;
    for (int i = gt; i < NN * (HD / 4); i += gsz)
        reinterpret_cast<float4*>(g_h)[i] = nf[i];
}

// ---------------- per-layer kernels ----------------------------------------

// K1 (#4 -> ncu capture slot): one warp per node, lane owns channels
// (2*lane, 2*lane+1). Edge metadata batch-loaded by lanes and broadcast via
// shfl. 2-warp blocks decouple stragglers.
__global__ void __launch_bounds__(64) k1_gather(const float* __restrict__ We,
                                                const float* __restrict__ be) {
    if (blockIdx.x == 0 && threadIdx.x < HD) {
        g_stats[threadIdx.x] = 0.f;
        g_stats[HD + threadIdx.x] = 0.f;
    }
    int n    = (blockIdx.x * blockDim.x + threadIdx.x) >> 5;
    int lane = threadIdx.x & 31;
    if (n >= NN) return;

    const float2* We2 = reinterpret_cast<const float2*>(We);
    const float2* be2 = reinterpret_cast<const float2*>(be);
    const float2* h2  = reinterpret_cast<const float2*>(g_h);
    float2 w0 = We2[0 * 32 + lane];
    float2 w1 = We2[1 * 32 + lane];
    float2 w2 = We2[2 * 32 + lane];
    float2 w3 = We2[3 * 32 + lane];
    float2 bb = be2[lane];

    int beg = g_rowptr[n], end = g_rowptr[n + 1];
    float2 a0 = h2[n * 32 + lane];
    float acc0 = a0.x, acc1 = a0.y;

    int j = beg;
    while (j < end) {
        int cnt = end - j;
        if (cnt > 32) cnt = 32;
        int s_l = 0;
        float4 f_l = make_float4(0.f, 0.f, 0.f, 0.f);
        if (lane < cnt) {
            s_l = g_srcs[j + lane];
            f_l = g_ef[j + lane];
        }
#pragma unroll 4
        for (int t = 0; t < cnt; ++t) {
            int   s  = __shfl_sync(0xffffffffu, s_l,   t);
            float fx = __shfl_sync(0xffffffffu, f_l.x, t);
            float fy = __shfl_sync(0xffffffffu, f_l.y, t);
            float fz = __shfl_sync(0xffffffffu, f_l.z, t);
            float fw = __shfl_sync(0xffffffffu, f_l.w, t);
            float2 v = h2[s * 32 + lane];
            float e0 = fmaf(fx, w0.x, fmaf(fy, w1.x, fmaf(fz, w2.x, fmaf(fw, w3.x, bb.x))));
            float e1 = fmaf(fx, w0.y, fmaf(fy, w1.y, fmaf(fz, w2.y, fmaf(fw, w3.y, bb.y))));
            acc0 += fmaxf(v.x + e0, 0.f);
            acc1 += fmaxf(v.y + e1, 0.f);
        }
        j += cnt;
    }
    reinterpret_cast<float2*>(g_z)[n * 32 + lane] = make_float2(acc0, acc1);
}

// K2: fused y = relu(z@W1+b1)@W2+b2 over a 64-row tile, plus BN batch stats.
// A rows pair NATURALLY in smem (one LDS.128 = two u64 row-pairs, no MOVs);
// W splatted in-register (4 MOVs/iter). 14 issues/k-iter vs 18 before.
#define K2_SMEM (64 * 68 * 4 + 64 * 64 * 4 + 128 * 4)
__global__ void __launch_bounds__(256, 6) k2_mlp(
    const float* __restrict__ W1, const float* __restrict__ b1,
    const float* __restrict__ W2, const float* __restrict__ b2) {
    extern __shared__ char smem_raw[];
    float* sA   = reinterpret_cast<float*>(smem_raw);            // [64][68]
    float* sW   = reinterpret_cast<float*>(smem_raw + 64 * 68 * 4);
    float* ssum = sW + 64 * 64;
    float* ssq  = ssum + 64;

    int tid = threadIdx.x;
    int rb  = blockIdx.x * 64;
    if (tid < 64) { ssum[tid] = 0.f; ssq[tid] = 0.f; }

    int tx = tid & 15, ty = tid >> 4;
    int c0 = tx * 4, r0 = ty * 4;

    // load z tile transposed: sA[k][r] = z[r][k]
    for (int itr = 0; itr < 4; ++itr) {
        int r = ty + itr * 16;
        float4 v = make_float4(0.f, 0.f, 0.f, 0.f);
        if (rb + r < NN) v = *reinterpret_cast<const float4*>(g_z + (rb + r) * 64 + c0);
        sA[(c0 + 0) * 68 + r] = v.x;
        sA[(c0 + 1) * 68 + r] = v.y;
        sA[(c0 + 2) * 68 + r] = v.z;
        sA[(c0 + 3) * 68 + r] = v.w;
    }
    for (int itr = 0; itr < 4; ++itr) {
        int idx = tid + itr * 256;
        reinterpret_cast<float4*>(sW)[idx] = __ldg(reinterpret_cast<const float4*>(W1) + idx);
    }
    __syncthreads();

    // ---- GEMM1: q[rp][c] pairs rows (r0,r0+1)/(r0+2,r0+3) against col c ----
    u64 q0 = 0, q1 = 0, q2 = 0, q3 = 0, q4 = 0, q5 = 0, q6 = 0, q7 = 0;
#pragma unroll 8
    for (int k = 0; k < 64; ++k) {
        ulonglong2 p = *reinterpret_cast<ulonglong2*>(&sA[k * 68 + r0]);  // rows r0..r0+3
        float4 wv    = *reinterpret_cast<float4*>(&sW[k * 64 + c0]);
        u64 ws0 = pk2(wv.x, wv.x), ws1 = pk2(wv.y, wv.y);
        u64 ws2 = pk2(wv.z, wv.z), ws3 = pk2(wv.w, wv.w);
        q0 = ffma2(p.x, ws0, q0); q1 = ffma2(p.x, ws1, q1);
        q2 = ffma2(p.x, ws2, q2); q3 = ffma2(p.x, ws3, q3);
        q4 = ffma2(p.y, ws0, q4); q5 = ffma2(p.y, ws1, q5);
        q6 = ffma2(p.y, ws2, q6); q7 = ffma2(p.y, ws3, q7);
    }
    float4 bb1 = __ldg(reinterpret_cast<const float4*>(b1 + c0));
    float tt[4][4];
    { float2 u = upk2(q0); tt[0][0] = u.x; tt[1][0] = u.y; }
    { float2 u = upk2(q1); tt[0][1] = u.x; tt[1][1] = u.y; }
    { float2 u = upk2(q2); tt[0][2] = u.x; tt[1][2] = u.y; }
    { float2 u = upk2(q3); tt[0][3] = u.x; tt[1][3] = u.y; }
    { float2 u = upk2(q4); tt[2][0] = u.x; tt[3][0] = u.y; }
    { float2 u = upk2(q5); tt[2][1] = u.x; tt[3][1] = u.y; }
    { float2 u = upk2(q6); tt[2][2] = u.x; tt[3][2] = u.y; }
    { float2 u = upk2(q7); tt[2][3] = u.x; tt[3][3] = u.y; }
#pragma unroll
    for (int i = 0; i < 4; ++i) {
        tt[i][0] = fmaxf(tt[i][0] + bb1.x, 0.f);
        tt[i][1] = fmaxf(tt[i][1] + bb1.y, 0.f);
        tt[i][2] = fmaxf(tt[i][2] + bb1.z, 0.f);
        tt[i][3] = fmaxf(tt[i][3] + bb1.w, 0.f);
    }
    __syncthreads();  // everyone done reading sA / sW

    // store t transposed (k index = channel c); reload sW with W2
#pragma unroll
    for (int i = 0; i < 4; ++i)
#pragma unroll
        for (int j = 0; j < 4; ++j)
            sA[(c0 + j) * 68 + (r0 + i)] = tt[i][j];
    for (int itr = 0; itr < 4; ++itr) {
        int idx = tid + itr * 256;
        reinterpret_cast<float4*>(sW)[idx] = __ldg(reinterpret_cast<const float4*>(W2) + idx);
    }
    __syncthreads();

    // ---- GEMM2 ----
    q0 = q1 = q2 = q3 = q4 = q5 = q6 = q7 = 0;
#pragma unroll 8
    for (int k = 0; k < 64; ++k) {
        ulonglong2 p = *reinterpret_cast<ulonglong2*>(&sA[k * 68 + r0]);
        float4 wv    = *reinterpret_cast<float4*>(&sW[k * 64 + c0]);
        u64 ws0 = pk2(wv.x, wv.x), ws1 = pk2(wv.y, wv.y);
        u64 ws2 = pk2(wv.z, wv.z), ws3 = pk2(wv.w, wv.w);
        q0 = ffma2(p.x, ws0, q0); q1 = ffma2(p.x, ws1, q1);
        q2 = ffma2(p.x, ws2, q2); q3 = ffma2(p.x, ws3, q3);
        q4 = ffma2(p.y, ws0, q4); q5 = ffma2(p.y, ws1, q5);
        q6 = ffma2(p.y, ws2, q6); q7 = ffma2(p.y, ws3, q7);
    }
    float4 bb2 = __ldg(reinterpret_cast<const float4*>(b2 + c0));
    float yy[4][4];
    { float2 u = upk2(q0); yy[0][0] = u.x + bb2.x; yy[1][0] = u.y + bb2.x; }
    { float2 u = upk2(q1); yy[0][1] = u.x + bb2.y; yy[1][1] = u.y + bb2.y; }
    { float2 u = upk2(q2); yy[0][2] = u.x + bb2.z; yy[1][2] = u.y + bb2.z; }
    { float2 u = upk2(q3); yy[0][3] = u.x + bb2.w; yy[1][3] = u.y + bb2.w; }
    { float2 u = upk2(q4); yy[2][0] = u.x + bb2.x; yy[3][0] = u.y + bb2.x; }
    { float2 u = upk2(q5); yy[2][1] = u.x + bb2.y; yy[3][1] = u.y + bb2.y; }
    { float2 u = upk2(q6); yy[2][2] = u.x + bb2.z; yy[3][2] = u.y + bb2.z; }
    { float2 u = upk2(q7); yy[2][3] = u.x + bb2.w; yy[3][3] = u.y + bb2.w; }

    // write y + accumulate stats
#pragma unroll
    for (int i = 0; i < 4; ++i) {
        int r = rb + r0 + i;
        if (r < NN) {
            float4 v = make_float4(yy[i][0], yy[i][1], yy[i][2], yy[i][3]);
            *reinterpret_cast<float4*>(g_y + r * 64 + c0) = v;
        }
    }
#pragma unroll
    for (int j = 0; j < 4; ++j) {
        float sj = 0.f, qj = 0.f;
#pragma unroll
        for (int i = 0; i < 4; ++i) {
            if (rb + r0 + i < NN) { sj += yy[i][j]; qj += yy[i][j] * yy[i][j]; }
        }
        atomicAdd(&ssum[c0 + j], sj);
        atomicAdd(&ssq[c0 + j], qj);
    }
    __syncthreads();
    if (tid < 64) {
        atomicAdd(&g_stats[tid], ssum[tid]);
        atomicAdd(&g_stats[64 + tid], ssq[tid]);
    }
}

// K4: BN finalize (per-block redundant) + h = relu(y*scale+shift) + h
__global__ void k4_post(const float* __restrict__ gamma, const float* __restrict__ beta,
                        float* __restrict__ out_final, int last) {
    __shared__ float s_sc[HD], s_sh[HD];
    int tid = threadIdx.x;
    if (tid < HD) {
        float mean = g_stats[tid] * (1.f / NN);
        float var  = g_stats[HD + tid] * (1.f / NN) - mean * mean;
        float inv  = rsqrtf(var + BN_EPS);
        float sc   = gamma[tid] * inv;
        s_sc[tid] = sc;
        s_sh[tid] = beta[tid] - mean * sc;
    }
    __syncthreads();
    int i = blockIdx.x * blockDim.x + tid;
    if (i >= NN * (HD / 4)) return;
    int c0 = (i & 15) * 4;
    float4 y  = reinterpret_cast<const float4*>(g_y)[i];
    float4 h  = reinterpret_cast<const float4*>(g_h)[i];
    float4 sc = *reinterpret_cast<const float4*>(&s_sc[c0]);
    float4 sh = *reinterpret_cast<const float4*>(&s_sh[c0]);
    float4 o;
    o.x = fmaxf(fmaf(y.x, sc.x, sh.x), 0.f) + h.x;
    o.y = fmaxf(fmaf(y.y, sc.y, sh.y), 0.f) + h.y;
    o.z = fmaxf(fmaf(y.z, sc.z, sh.z), 0.f) + h.z;
    o.w = fmaxf(fmaf(y.w, sc.w, sh.w), 0.f) + h.w;
    float4* dst = last ? reinterpret_cast<float4*>(out_final)
                       : reinterpret_cast<float4*>(g_h);
    dst[i] = o;
}

// ---------------- launch ----------------------------------------------------

extern "C" void kernel_launch(void* const* d_in, const int* in_sizes, int n_in,
                              void* d_out, int out_size) {
    const float* node_feat = (const float*)d_in[0];
    const float* edge_feat = (const float*)d_in[1];
    const int*   src       = (const int*)d_in[2];
    const int*   dst       = (const int*)d_in[3];
    const float* We        = (const float*)d_in[4];
    const float* be        = (const float*)d_in[5];
    const float* W1        = (const float*)d_in[6];
    const float* b1        = (const float*)d_in[7];
    const float* W2        = (const float*)d_in[8];
    const float* b2        = (const float*)d_in[9];
    const float* gamma     = (const float*)d_in[10];
    const float* beta      = (const float*)d_in[11];
    float* out = (float*)d_out;

    cudaFuncSetAttribute(k2_mlp, cudaFuncAttributeMaxDynamicSharedMemorySize, K2_SMEM);

    const int T = 256;
    k_hist<<<(NE + T - 1) / T, T>>>(dst);
    k_scan1<<<NCHUNKS, 512>>>();
    k_scatter<<<(NE + T - 1) / T, T>>>(src, dst,
                                       reinterpret_cast<const float4*>(edge_feat),
                                       reinterpret_cast<const float4*>(node_feat));

    for (int l = 0; l < 4; ++l) {
        k1_gather<<<NN / 2, 64>>>(We, be);
        k2_mlp<<<(NN + 63) / 64, 256, K2_SMEM>>>(W1 + l * HD * HD, b1 + l * HD,
                                                 W2 + l * HD * HD, b2 + l * HD);
        k4_post<<<(NN * 16 + T - 1) / T, T>>>(gamma + l * HD, beta + l * HD,
                                              out, l == 3 ? 1 : 0);
    }
}

// round 10
// speedup vs baseline: 1.0064x; 1.0064x over previous
#include <cuda_runtime.h>

#define NN 100000
#define NE 1600000
#define HD 64
#define BN_EPS 1e-5f
#define NCHUNKS 25   // ceil(NN/4096)

// ---------------- scratch (device globals; no runtime allocation) ----------
static __device__ __align__(16) float g_h[NN * HD];   // running node features
static __device__ __align__(16) float g_z[NN * HD];   // h + aggregation
static __device__ __align__(16) float g_y[NN * HD];   // MLP output (pre-BN)
static __device__ int    g_srcs[NE];                  // src sorted by dst (CSR)
static __device__ float4 g_ef[NE];                    // edge features sorted by dst
static __device__ int    g_deg[NN];                   // zero at entry (invariant)
static __device__ int    g_wcur[NN];                  // zero at entry (invariant)
static __device__ int    g_rowloc[NN];                // chunk-local prefix
static __device__ int    g_rowptr[NN + 1];            // final CSR rowptr
static __device__ int    g_part[32];                  // per-chunk edge totals
static __device__ float  g_stats[2 * HD];             // per-channel sum / sumsq

typedef unsigned long long u64;

__device__ __forceinline__ u64 pk2(float x, float y) {
    u64 r; asm("mov.b64 %0,{%1,%2};" : "=l"(r) : "f"(x), "f"(y)); return r;
}
__device__ __forceinline__ float2 upk2(u64 a) {
    float2 r; asm("mov.b64 {%0,%1},%2;" : "=f"(r.x), "=f"(r.y) : "l"(a)); return r;
}
__device__ __forceinline__ u64 ffma2(u64 a, u64 b, u64 c) {
    u64 d; asm("fma.rn.f32x2 %0,%1,%2,%3;" : "=l"(d) : "l"(a), "l"(b), "l"(c)); return d;
}

// ---------------- preprocessing (3 launches) --------------------------------

__global__ void k_hist(const int* __restrict__ dst) {
    int i = blockIdx.x * blockDim.x + threadIdx.x;
    if (i < NE) atomicAdd(&g_deg[dst[i]], 1);
}

__global__ void __launch_bounds__(512, 1) k_scan1() {
    __shared__ int s[512];
    int tid = threadIdx.x;
    int base = blockIdx.x * 4096 + tid * 8;
    int items[8]; int t = 0;
#pragma unroll
    for (int j = 0; j < 8; ++j) {
        int idx = base + j;
        int v = 0;
        if (idx < NN) { v = g_deg[idx]; g_deg[idx] = 0; g_wcur[idx] = 0; }
        items[j] = v; t += v;
    }
    s[tid] = t;
    __syncthreads();
    for (int off = 1; off < 512; off <<= 1) {
        int x = (tid >= off) ? s[tid - off] : 0;
        __syncthreads();
        s[tid] += x;
        __syncthreads();
    }
    int run = s[tid] - t;
#pragma unroll
    for (int j = 0; j < 8; ++j) {
        int idx = base + j;
        if (idx < NN) g_rowloc[idx] = run;
        run += items[j];
    }
    if (tid == 511) g_part[blockIdx.x] = s[511];
}

__global__ void k_scatter(const int* __restrict__ src, const int* __restrict__ dst,
                          const float4* __restrict__ ef, const float4* __restrict__ nf) {
    __shared__ int s_off[32];
    if (threadIdx.x < 32) {
        int orig = (threadIdx.x < NCHUNKS) ? g_part[threadIdx.x] : 0;
        int v = orig;
        for (int off = 1; off < 32; off <<= 1) {
            int x = __shfl_up_sync(0xffffffffu, v, off);
            if ((threadIdx.x & 31) >= off) v += x;
        }
        s_off[threadIdx.x] = v - orig;  // exclusive prefix
    }
    __syncthreads();
    int gt = blockIdx.x * blockDim.x + threadIdx.x;
    int gsz = gridDim.x * blockDim.x;
    for (int i = gt; i < NE; i += gsz) {
        int d = dst[i];
        int pos = g_rowloc[d] + s_off[d >> 12] + atomicAdd(&g_wcur[d], 1);
        g_srcs[pos] = src[i];
        g_ef[pos]   = ef[i];
    }
    for (int i = gt; i < NN; i += gsz)
        g_rowptr[i] = g_rowloc[i] + s_off[i >> 12];
    if (gt == 0) g_rowptr[NN] = NE;
    for (int i = gt; i < NN * (HD / 4); i += gsz)
        reinterpret_cast<float4*>(g_h)[i] = nf[i];
}

// ---------------- per-layer kernels ----------------------------------------

// K1 (#4 -> ncu capture slot): one warp per node, lane owns channels
// (2*lane, 2*lane+1). Edge metadata batch-loaded by lanes and broadcast via
// shfl. 2-warp blocks decouple stragglers.
__global__ void __launch_bounds__(64) k1_gather(const float* __restrict__ We,
                                                const float* __restrict__ be) {
    if (blockIdx.x == 0 && threadIdx.x < HD) {
        g_stats[threadIdx.x] = 0.f;
        g_stats[HD + threadIdx.x] = 0.f;
    }
    int n    = (blockIdx.x * blockDim.x + threadIdx.x) >> 5;
    int lane = threadIdx.x & 31;
    if (n >= NN) return;

    const float2* We2 = reinterpret_cast<const float2*>(We);
    const float2* be2 = reinterpret_cast<const float2*>(be);
    const float2* h2  = reinterpret_cast<const float2*>(g_h);
    float2 w0 = We2[0 * 32 + lane];
    float2 w1 = We2[1 * 32 + lane];
    float2 w2 = We2[2 * 32 + lane];
    float2 w3 = We2[3 * 32 + lane];
    float2 bb = be2[lane];

    int beg = g_rowptr[n], end = g_rowptr[n + 1];
    float2 a0 = h2[n * 32 + lane];
    float acc0 = a0.x, acc1 = a0.y;

    int j = beg;
    while (j < end) {
        int cnt = end - j;
        if (cnt > 32) cnt = 32;
        int s_l = 0;
        float4 f_l = make_float4(0.f, 0.f, 0.f, 0.f);
        if (lane < cnt) {
            s_l = g_srcs[j + lane];
            f_l = g_ef[j + lane];
        }
#pragma unroll 4
        for (int t = 0; t < cnt; ++t) {
            int   s  = __shfl_sync(0xffffffffu, s_l,   t);
            float fx = __shfl_sync(0xffffffffu, f_l.x, t);
            float fy = __shfl_sync(0xffffffffu, f_l.y, t);
            float fz = __shfl_sync(0xffffffffu, f_l.z, t);
            float fw = __shfl_sync(0xffffffffu, f_l.w, t);
            float2 v = h2[s * 32 + lane];
            float e0 = fmaf(fx, w0.x, fmaf(fy, w1.x, fmaf(fz, w2.x, fmaf(fw, w3.x, bb.x))));
            float e1 = fmaf(fx, w0.y, fmaf(fy, w1.y, fmaf(fz, w2.y, fmaf(fw, w3.y, bb.y))));
            acc0 += fmaxf(v.x + e0, 0.f);
            acc1 += fmaxf(v.y + e1, 0.f);
        }
        j += cnt;
    }
    reinterpret_cast<float2*>(g_z)[n * 32 + lane] = make_float2(acc0, acc1);
}

// K2: fused y = relu(z@W1+b1)@W2+b2 over a 64-row tile, plus BN batch stats.
// A rows pair NATURALLY in smem (one LDS.128 = two u64 row-pairs, no MOVs);
// W splatted in-register (4 MOVs/iter). 14 issues/k-iter vs 18 before.
#define K2_SMEM (64 * 68 * 4 + 64 * 64 * 4 + 128 * 4)
__global__ void __launch_bounds__(256, 6) k2_mlp(
    const float* __restrict__ W1, const float* __restrict__ b1,
    const float* __restrict__ W2, const float* __restrict__ b2) {
    extern __shared__ char smem_raw[];
    float* sA   = reinterpret_cast<float*>(smem_raw);            // [64][68]
    float* sW   = reinterpret_cast<float*>(smem_raw + 64 * 68 * 4);
    float* ssum = sW + 64 * 64;
    float* ssq  = ssum + 64;

    int tid = threadIdx.x;
    int rb  = blockIdx.x * 64;
    if (tid < 64) { ssum[tid] = 0.f; ssq[tid] = 0.f; }

    int tx = tid & 15, ty = tid >> 4;
    int c0 = tx * 4, r0 = ty * 4;

    // load z tile transposed: sA[k][r] = z[r][k]
    for (int itr = 0; itr < 4; ++itr) {
        int r = ty + itr * 16;
        float4 v = make_float4(0.f, 0.f, 0.f, 0.f);
        if (rb + r < NN) v = *reinterpret_cast<const float4*>(g_z + (rb + r) * 64 + c0);
        sA[(c0 + 0) * 68 + r] = v.x;
        sA[(c0 + 1) * 68 + r] = v.y;
        sA[(c0 + 2) * 68 + r] = v.z;
        sA[(c0 + 3) * 68 + r] = v.w;
    }
    for (int itr = 0; itr < 4; ++itr) {
        int idx = tid + itr * 256;
        reinterpret_cast<float4*>(sW)[idx] = __ldg(reinterpret_cast<const float4*>(W1) + idx);
    }
    __syncthreads();

    // ---- GEMM1: q[rp][c] pairs rows (r0,r0+1)/(r0+2,r0+3) against col c ----
    u64 q0 = 0, q1 = 0, q2 = 0, q3 = 0, q4 = 0, q5 = 0, q6 = 0, q7 = 0;
#pragma unroll 8
    for (int k = 0; k < 64; ++k) {
        ulonglong2 p = *reinterpret_cast<ulonglong2*>(&sA[k * 68 + r0]);  // rows r0..r0+3
        float4 wv    = *reinterpret_cast<float4*>(&sW[k * 64 + c0]);
        u64 ws0 = pk2(wv.x, wv.x), ws1 = pk2(wv.y, wv.y);
        u64 ws2 = pk2(wv.z, wv.z), ws3 = pk2(wv.w, wv.w);
        q0 = ffma2(p.x, ws0, q0); q1 = ffma2(p.x, ws1, q1);
        q2 = ffma2(p.x, ws2, q2); q3 = ffma2(p.x, ws3, q3);
        q4 = ffma2(p.y, ws0, q4); q5 = ffma2(p.y, ws1, q5);
        q6 = ffma2(p.y, ws2, q6); q7 = ffma2(p.y, ws3, q7);
    }
    float4 bb1 = __ldg(reinterpret_cast<const float4*>(b1 + c0));
    float tt[4][4];
    { float2 u = upk2(q0); tt[0][0] = u.x; tt[1][0] = u.y; }
    { float2 u = upk2(q1); tt[0][1] = u.x; tt[1][1] = u.y; }
    { float2 u = upk2(q2); tt[0][2] = u.x; tt[1][2] = u.y; }
    { float2 u = upk2(q3); tt[0][3] = u.x; tt[1][3] = u.y; }
    { float2 u = upk2(q4); tt[2][0] = u.x; tt[3][0] = u.y; }
    { float2 u = upk2(q5); tt[2][1] = u.x; tt[3][1] = u.y; }
    { float2 u = upk2(q6); tt[2][2] = u.x; tt[3][2] = u.y; }
    { float2 u = upk2(q7); tt[2][3] = u.x; tt[3][3] = u.y; }
#pragma unroll
    for (int i = 0; i < 4; ++i) {
        tt[i][0] = fmaxf(tt[i][0] + bb1.x, 0.f);
        tt[i][1] = fmaxf(tt[i][1] + bb1.y, 0.f);
        tt[i][2] = fmaxf(tt[i][2] + bb1.z, 0.f);
        tt[i][3] = fmaxf(tt[i][3] + bb1.w, 0.f);
    }
    __syncthreads();  // everyone done reading sA / sW

    // store t transposed (k index = channel c); reload sW with W2
#pragma unroll
    for (int i = 0; i < 4; ++i)
#pragma unroll
        for (int j = 0; j < 4; ++j)
            sA[(c0 + j) * 68 + (r0 + i)] = tt[i][j];
    for (int itr = 0; itr < 4; ++itr) {
        int idx = tid + itr * 256;
        reinterpret_cast<float4*>(sW)[idx] = __ldg(reinterpret_cast<const float4*>(W2) + idx);
    }
    __syncthreads();

    // ---- GEMM2 ----
    q0 = q1 = q2 = q3 = q4 = q5 = q6 = q7 = 0;
#pragma unroll 8
    for (int k = 0; k < 64; ++k) {
        ulonglong2 p = *reinterpret_cast<ulonglong2*>(&sA[k * 68 + r0]);
        float4 wv    = *reinterpret_cast<float4*>(&sW[k * 64 + c0]);
        u64 ws0 = pk2(wv.x, wv.x), ws1 = pk2(wv.y, wv.y);
        u64 ws2 = pk2(wv.z, wv.z), ws3 = pk2(wv.w, wv.w);
        q0 = ffma2(p.x, ws0, q0); q1 = ffma2(p.x, ws1, q1);
        q2 = ffma2(p.x, ws2, q2); q3 = ffma2(p.x, ws3, q3);
        q4 = ffma2(p.y, ws0, q4); q5 = ffma2(p.y, ws1, q5);
        q6 = ffma2(p.y, ws2, q6); q7 = ffma2(p.y, ws3, q7);
    }
    float4 bb2 = __ldg(reinterpret_cast<const float4*>(b2 + c0));
    float yy[4][4];
    { float2 u = upk2(q0); yy[0][0] = u.x + bb2.x; yy[1][0] = u.y + bb2.x; }
    { float2 u = upk2(q1); yy[0][1] = u.x + bb2.y; yy[1][1] = u.y + bb2.y; }
    { float2 u = upk2(q2); yy[0][2] = u.x + bb2.z; yy[1][2] = u.y + bb2.z; }
    { float2 u = upk2(q3); yy[0][3] = u.x + bb2.w; yy[1][3] = u.y + bb2.w; }
    { float2 u = upk2(q4); yy[2][0] = u.x + bb2.x; yy[3][0] = u.y + bb2.x; }
    { float2 u = upk2(q5); yy[2][1] = u.x + bb2.y; yy[3][1] = u.y + bb2.y; }
    { float2 u = upk2(q6); yy[2][2] = u.x + bb2.z; yy[3][2] = u.y + bb2.z; }
    { float2 u = upk2(q7); yy[2][3] = u.x + bb2.w; yy[3][3] = u.y + bb2.w; }

    // write y + accumulate stats
#pragma unroll
    for (int i = 0; i < 4; ++i) {
        int r = rb + r0 + i;
        if (r < NN) {
            float4 v = make_float4(yy[i][0], yy[i][1], yy[i][2], yy[i][3]);
            *reinterpret_cast<float4*>(g_y + r * 64 + c0) = v;
        }
    }
#pragma unroll
    for (int j = 0; j < 4; ++j) {
        float sj = 0.f, qj = 0.f;
#pragma unroll
        for (int i = 0; i < 4; ++i) {
            if (rb + r0 + i < NN) { sj += yy[i][j]; qj += yy[i][j] * yy[i][j]; }
        }
        atomicAdd(&ssum[c0 + j], sj);
        atomicAdd(&ssq[c0 + j], qj);
    }
    __syncthreads();
    if (tid < 64) {
        atomicAdd(&g_stats[tid], ssum[tid]);
        atomicAdd(&g_stats[64 + tid], ssq[tid]);
    }
}

// K4: BN finalize (per-block redundant) + h = relu(y*scale+shift) + h
__global__ void k4_post(const float* __restrict__ gamma, const float* __restrict__ beta,
                        float* __restrict__ out_final, int last) {
    __shared__ float s_sc[HD], s_sh[HD];
    int tid = threadIdx.x;
    if (tid < HD) {
        float mean = g_stats[tid] * (1.f / NN);
        float var  = g_stats[HD + tid] * (1.f / NN) - mean * mean;
        float inv  = rsqrtf(var + BN_EPS);
        float sc   = gamma[tid] * inv;
        s_sc[tid] = sc;
        s_sh[tid] = beta[tid] - mean * sc;
    }
    __syncthreads();
    int i = blockIdx.x * blockDim.x + tid;
    if (i >= NN * (HD / 4)) return;
    int c0 = (i & 15) * 4;
    float4 y  = reinterpret_cast<const float4*>(g_y)[i];
    float4 h  = reinterpret_cast<const float4*>(g_h)[i];
    float4 sc = *reinterpret_cast<const float4*>(&s_sc[c0]);
    float4 sh = *reinterpret_cast<const float4*>(&s_sh[c0]);
    float4 o;
    o.x = fmaxf(fmaf(y.x, sc.x, sh.x), 0.f) + h.x;
    o.y = fmaxf(fmaf(y.y, sc.y, sh.y), 0.f) + h.y;
    o.z = fmaxf(fmaf(y.z, sc.z, sh.z), 0.f) + h.z;
    o.w = fmaxf(fmaf(y.w, sc.w, sh.w), 0.f) + h.w;
    float4* dst = last ? reinterpret_cast<float4*>(out_final)
                       : reinterpret_cast<float4*>(g_h);
    dst[i] = o;
}

// ---------------- launch ----------------------------------------------------

extern "C" void kernel_launch(void* const* d_in, const int* in_sizes, int n_in,
                              void* d_out, int out_size) {
    const float* node_feat = (const float*)d_in[0];
    const float* edge_feat = (const float*)d_in[1];
    const int*   src       = (const int*)d_in[2];
    const int*   dst       = (const int*)d_in[3];
    const float* We        = (const float*)d_in[4];
    const float* be        = (const float*)d_in[5];
    const float* W1        = (const float*)d_in[6];
    const float* b1        = (const float*)d_in[7];
    const float* W2        = (const float*)d_in[8];
    const float* b2        = (const float*)d_in[9];
    const float* gamma     = (const float*)d_in[10];
    const float* beta      = (const float*)d_in[11];
    float* out = (float*)d_out;

    cudaFuncSetAttribute(k2_mlp, cudaFuncAttributeMaxDynamicSharedMemorySize, K2_SMEM);

    const int T = 256;
    k_hist<<<(NE + T - 1) / T, T>>>(dst);
    k_scan1<<<NCHUNKS, 512>>>();
    k_scatter<<<(NE + T - 1) / T, T>>>(src, dst,
                                       reinterpret_cast<const float4*>(edge_feat),
                                       reinterpret_cast<const float4*>(node_feat));

    for (int l = 0; l < 4; ++l) {
        k1_gather<<<NN / 2, 64>>>(We, be);
        k2_mlp<<<(NN + 63) / 64, 256, K2_SMEM>>>(W1 + l * HD * HD, b1 + l * HD,
                                                 W2 + l * HD * HD, b2 + l * HD);
        k4_post<<<(NN * 16 + T - 1) / T, T>>>(gamma + l * HD, beta + l * HD,
                                              out, l == 3 ? 1 : 0);
    }
}

// round 12
// speedup vs baseline: 1.0065x; 1.0001x over previous
#include <cuda_runtime.h>

#define NN 100000
#define NE 1600000
#define HD 64
#define BN_EPS 1e-5f
#define NCHUNKS 25   // ceil(NN/4096)

// ---------------- scratch (device globals; no runtime allocation) ----------
static __device__ __align__(16) float g_h[NN * HD];   // running node features
static __device__ __align__(16) float g_z[NN * HD];   // h + aggregation
static __device__ __align__(16) float g_y[NN * HD];   // MLP output (pre-BN)
static __device__ int    g_srcs[NE];                  // src sorted by dst (CSR)
static __device__ float4 g_ef[NE];                    // edge features sorted by dst
static __device__ int    g_deg[NN];                   // zero at entry (invariant)
static __device__ int    g_wcur[NN];                  // zero at entry (invariant)
static __device__ int    g_rowloc[NN];                // chunk-local prefix
static __device__ int    g_rowptr[NN + 1];            // final CSR rowptr
static __device__ int    g_part[32];                  // per-chunk edge totals
static __device__ float  g_stats[2 * HD];             // per-channel sum / sumsq

typedef unsigned long long u64;

__device__ __forceinline__ u64 pk2(float x, float y) {
    u64 r; asm("mov.b64 %0,{%1,%2};" : "=l"(r) : "f"(x), "f"(y)); return r;
}
__device__ __forceinline__ float2 upk2(u64 a) {
    float2 r; asm("mov.b64 {%0,%1},%2;" : "=f"(r.x), "=f"(r.y) : "l"(a)); return r;
}
__device__ __forceinline__ u64 ffma2(u64 a, u64 b, u64 c) {
    u64 d; asm("fma.rn.f32x2 %0,%1,%2,%3;" : "=l"(d) : "l"(a), "l"(b), "l"(c)); return d;
}

// ---------------- preprocessing (3 launches) --------------------------------

__global__ void k_hist(const int* __restrict__ dst) {
    int i = blockIdx.x * blockDim.x + threadIdx.x;
    if (i < NE) atomicAdd(&g_deg[dst[i]], 1);
}

__global__ void __launch_bounds__(512, 1) k_scan1() {
    __shared__ int s[512];
    int tid = threadIdx.x;
    int base = blockIdx.x * 4096 + tid * 8;
    int items[8]; int t = 0;
#pragma unroll
    for (int j = 0; j < 8; ++j) {
        int idx = base + j;
        int v = 0;
        if (idx < NN) { v = g_deg[idx]; g_deg[idx] = 0; g_wcur[idx] = 0; }
        items[j] = v; t += v;
    }
    s[tid] = t;
    __syncthreads();
    for (int off = 1; off < 512; off <<= 1) {
        int x = (tid >= off) ? s[tid - off] : 0;
        __syncthreads();
        s[tid] += x;
        __syncthreads();
    }
    int run = s[tid] - t;
#pragma unroll
    for (int j = 0; j < 8; ++j) {
        int idx = base + j;
        if (idx < NN) g_rowloc[idx] = run;
        run += items[j];
    }
    if (tid == 511) g_part[blockIdx.x] = s[511];
}

__global__ void k_scatter(const int* __restrict__ src, const int* __restrict__ dst,
                          const float4* __restrict__ ef, const float4* __restrict__ nf) {
    __shared__ int s_off[32];
    if (threadIdx.x < 32) {
        int orig = (threadIdx.x < NCHUNKS) ? g_part[threadIdx.x] : 0;
        int v = orig;
        for (int off = 1; off < 32; off <<= 1) {
            int x = __shfl_up_sync(0xffffffffu, v, off);
            if ((threadIdx.x & 31) >= off) v += x;
        }
        s_off[threadIdx.x] = v - orig;  // exclusive prefix
    }
    __syncthreads();
    int gt = blockIdx.x * blockDim.x + threadIdx.x;
    int gsz = gridDim.x * blockDim.x;
    for (int i = gt; i < NE; i += gsz) {
        int d = dst[i];
        int pos = g_rowloc[d] + s_off[d >> 12] + atomicAdd(&g_wcur[d], 1);
        g_srcs[pos] = src[i];
        g_ef[pos]   = ef[i];
    }
    for (int i = gt; i < NN; i += gsz)
        g_rowptr[i] = g_rowloc[i] + s_off[i >> 12];
    if (gt == 0) g_rowptr[NN] = NE;
    for (int i = gt; i < NN * (HD / 4); i += gsz)
        reinterpret_cast<float4*>(g_h)[i] = nf[i];
}

// ---------------- per-layer kernels ----------------------------------------

// K1 (#4 -> ncu capture slot): one warp per node, lane owns channels
// (2*lane, 2*lane+1). Edge metadata batch-loaded by lanes and broadcast via
// shfl. 2-warp blocks decouple stragglers.
__global__ void __launch_bounds__(64) k1_gather(const float* __restrict__ We,
                                                const float* __restrict__ be) {
    if (blockIdx.x == 0 && threadIdx.x < HD) {
        g_stats[threadIdx.x] = 0.f;
        g_stats[HD + threadIdx.x] = 0.f;
    }
    int n    = (blockIdx.x * blockDim.x + threadIdx.x) >> 5;
    int lane = threadIdx.x & 31;
    if (n >= NN) return;

    const float2* We2 = reinterpret_cast<const float2*>(We);
    const float2* be2 = reinterpret_cast<const float2*>(be);
    const float2* h2  = reinterpret_cast<const float2*>(g_h);
    float2 w0 = We2[0 * 32 + lane];
    float2 w1 = We2[1 * 32 + lane];
    float2 w2 = We2[2 * 32 + lane];
    float2 w3 = We2[3 * 32 + lane];
    float2 bb = be2[lane];

    int beg = g_rowptr[n], end = g_rowptr[n + 1];
    float2 a0 = h2[n * 32 + lane];
    float acc0 = a0.x, acc1 = a0.y;

    int j = beg;
    while (j < end) {
        int cnt = end - j;
        if (cnt > 32) cnt = 32;
        int s_l = 0;
        float4 f_l = make_float4(0.f, 0.f, 0.f, 0.f);
        if (lane < cnt) {
            s_l = g_srcs[j + lane];
            f_l = g_ef[j + lane];
        }
#pragma unroll 4
        for (int t = 0; t < cnt; ++t) {
            int   s  = __shfl_sync(0xffffffffu, s_l,   t);
            float fx = __shfl_sync(0xffffffffu, f_l.x, t);
            float fy = __shfl_sync(0xffffffffu, f_l.y, t);
            float fz = __shfl_sync(0xffffffffu, f_l.z, t);
            float fw = __shfl_sync(0xffffffffu, f_l.w, t);
            float2 v = h2[s * 32 + lane];
            float e0 = fmaf(fx, w0.x, fmaf(fy, w1.x, fmaf(fz, w2.x, fmaf(fw, w3.x, bb.x))));
            float e1 = fmaf(fx, w0.y, fmaf(fy, w1.y, fmaf(fz, w2.y, fmaf(fw, w3.y, bb.y))));
            acc0 += fmaxf(v.x + e0, 0.f);
            acc1 += fmaxf(v.y + e1, 0.f);
        }
        j += cnt;
    }
    reinterpret_cast<float2*>(g_z)[n * 32 + lane] = make_float2(acc0, acc1);
}

// K2: fused y = relu(z@W1+b1)@W2+b2 over a 64-row tile, plus BN batch stats.
// A rows pair NATURALLY in smem (one LDS.128 = two u64 row-pairs, no MOVs);
// W splatted in-register (4 MOVs/iter). 14 issues/k-iter vs 18 before.
#define K2_SMEM (64 * 68 * 4 + 64 * 64 * 4 + 128 * 4)
__global__ void __launch_bounds__(256, 6) k2_mlp(
    const float* __restrict__ W1, const float* __restrict__ b1,
    const float* __restrict__ W2, const float* __restrict__ b2) {
    extern __shared__ char smem_raw[];
    float* sA   = reinterpret_cast<float*>(smem_raw);            // [64][68]
    float* sW   = reinterpret_cast<float*>(smem_raw + 64 * 68 * 4);
    float* ssum = sW + 64 * 64;
    float* ssq  = ssum + 64;

    int tid = threadIdx.x;
    int rb  = blockIdx.x * 64;
    if (tid < 64) { ssum[tid] = 0.f; ssq[tid] = 0.f; }

    int tx = tid & 15, ty = tid >> 4;
    int c0 = tx * 4, r0 = ty * 4;

    // load z tile transposed: sA[k][r] = z[r][k]
    for (int itr = 0; itr < 4; ++itr) {
        int r = ty + itr * 16;
        float4 v = make_float4(0.f, 0.f, 0.f, 0.f);
        if (rb + r < NN) v = *reinterpret_cast<const float4*>(g_z + (rb + r) * 64 + c0);
        sA[(c0 + 0) * 68 + r] = v.x;
        sA[(c0 + 1) * 68 + r] = v.y;
        sA[(c0 + 2) * 68 + r] = v.z;
        sA[(c0 + 3) * 68 + r] = v.w;
    }
    for (int itr = 0; itr < 4; ++itr) {
        int idx = tid + itr * 256;
        reinterpret_cast<float4*>(sW)[idx] = __ldg(reinterpret_cast<const float4*>(W1) + idx);
    }
    __syncthreads();

    // ---- GEMM1: q[rp][c] pairs rows (r0,r0+1)/(r0+2,r0+3) against col c ----
    u64 q0 = 0, q1 = 0, q2 = 0, q3 = 0, q4 = 0, q5 = 0, q6 = 0, q7 = 0;
#pragma unroll 8
    for (int k = 0; k < 64; ++k) {
        ulonglong2 p = *reinterpret_cast<ulonglong2*>(&sA[k * 68 + r0]);  // rows r0..r0+3
        float4 wv    = *reinterpret_cast<float4*>(&sW[k * 64 + c0]);
        u64 ws0 = pk2(wv.x, wv.x), ws1 = pk2(wv.y, wv.y);
        u64 ws2 = pk2(wv.z, wv.z), ws3 = pk2(wv.w, wv.w);
        q0 = ffma2(p.x, ws0, q0); q1 = ffma2(p.x, ws1, q1);
        q2 = ffma2(p.x, ws2, q2); q3 = ffma2(p.x, ws3, q3);
        q4 = ffma2(p.y, ws0, q4); q5 = ffma2(p.y, ws1, q5);
        q6 = ffma2(p.y, ws2, q6); q7 = ffma2(p.y, ws3, q7);
    }
    float4 bb1 = __ldg(reinterpret_cast<const float4*>(b1 + c0));
    float tt[4][4];
    { float2 u = upk2(q0); tt[0][0] = u.x; tt[1][0] = u.y; }
    { float2 u = upk2(q1); tt[0][1] = u.x; tt[1][1] = u.y; }
    { float2 u = upk2(q2); tt[0][2] = u.x; tt[1][2] = u.y; }
    { float2 u = upk2(q3); tt[0][3] = u.x; tt[1][3] = u.y; }
    { float2 u = upk2(q4); tt[2][0] = u.x; tt[3][0] = u.y; }
    { float2 u = upk2(q5); tt[2][1] = u.x; tt[3][1] = u.y; }
    { float2 u = upk2(q6); tt[2][2] = u.x; tt[3][2] = u.y; }
    { float2 u = upk2(q7); tt[2][3] = u.x; tt[3][3] = u.y; }
#pragma unroll
    for (int i = 0; i < 4; ++i) {
        tt[i][0] = fmaxf(tt[i][0] + bb1.x, 0.f);
        tt[i][1] = fmaxf(tt[i][1] + bb1.y, 0.f);
        tt[i][2] = fmaxf(tt[i][2] + bb1.z, 0.f);
        tt[i][3] = fmaxf(tt[i][3] + bb1.w, 0.f);
    }
    __syncthreads();  // everyone done reading sA / sW

    // store t transposed (k index = channel c); reload sW with W2
#pragma unroll
    for (int i = 0; i < 4; ++i)
#pragma unroll
        for (int j = 0; j < 4; ++j)
            sA[(c0 + j) * 68 + (r0 + i)] = tt[i][j];
    for (int itr = 0; itr < 4; ++itr) {
        int idx = tid + itr * 256;
        reinterpret_cast<float4*>(sW)[idx] = __ldg(reinterpret_cast<const float4*>(W2) + idx);
    }
    __syncthreads();

    // ---- GEMM2 ----
    q0 = q1 = q2 = q3 = q4 = q5 = q6 = q7 = 0;
#pragma unroll 8
    for (int k = 0; k < 64; ++k) {
        ulonglong2 p = *reinterpret_cast<ulonglong2*>(&sA[k * 68 + r0]);
        float4 wv    = *reinterpret_cast<float4*>(&sW[k * 64 + c0]);
        u64 ws0 = pk2(wv.x, wv.x), ws1 = pk2(wv.y, wv.y);
        u64 ws2 = pk2(wv.z, wv.z), ws3 = pk2(wv.w, wv.w);
        q0 = ffma2(p.x, ws0, q0); q1 = ffma2(p.x, ws1, q1);
        q2 = ffma2(p.x, ws2, q2); q3 = ffma2(p.x, ws3, q3);
        q4 = ffma2(p.y, ws0, q4); q5 = ffma2(p.y, ws1, q5);
        q6 = ffma2(p.y, ws2, q6); q7 = ffma2(p.y, ws3, q7);
    }
    float4 bb2 = __ldg(reinterpret_cast<const float4*>(b2 + c0));
    float yy[4][4];
    { float2 u = upk2(q0); yy[0][0] = u.x + bb2.x; yy[1][0] = u.y + bb2.x; }
    { float2 u = upk2(q1); yy[0][1] = u.x + bb2.y; yy[1][1] = u.y + bb2.y; }
    { float2 u = upk2(q2); yy[0][2] = u.x + bb2.z; yy[1][2] = u.y + bb2.z; }
    { float2 u = upk2(q3); yy[0][3] = u.x + bb2.w; yy[1][3] = u.y + bb2.w; }
    { float2 u = upk2(q4); yy[2][0] = u.x + bb2.x; yy[3][0] = u.y + bb2.x; }
    { float2 u = upk2(q5); yy[2][1] = u.x + bb2.y; yy[3][1] = u.y + bb2.y; }
    { float2 u = upk2(q6); yy[2][2] = u.x + bb2.z; yy[3][2] = u.y + bb2.z; }
    { float2 u = upk2(q7); yy[2][3] = u.x + bb2.w; yy[3][3] = u.y + bb2.w; }

    // write y + accumulate stats
#pragma unroll
    for (int i = 0; i < 4; ++i) {
        int r = rb + r0 + i;
        if (r < NN) {
            float4 v = make_float4(yy[i][0], yy[i][1], yy[i][2], yy[i][3]);
            *reinterpret_cast<float4*>(g_y + r * 64 + c0) = v;
        }
    }
#pragma unroll
    for (int j = 0; j < 4; ++j) {
        float sj = 0.f, qj = 0.f;
#pragma unroll
        for (int i = 0; i < 4; ++i) {
            if (rb + r0 + i < NN) { sj += yy[i][j]; qj += yy[i][j] * yy[i][j]; }
        }
        atomicAdd(&ssum[c0 + j], sj);
        atomicAdd(&ssq[c0 + j], qj);
    }
    __syncthreads();
    if (tid < 64) {
        atomicAdd(&g_stats[tid], ssum[tid]);
        atomicAdd(&g_stats[64 + tid], ssq[tid]);
    }
}

// K4: BN finalize (per-block redundant) + h = relu(y*scale+shift) + h
__global__ void k4_post(const float* __restrict__ gamma, const float* __restrict__ beta,
                        float* __restrict__ out_final, int last) {
    __shared__ float s_sc[HD], s_sh[HD];
    int tid = threadIdx.x;
    if (tid < HD) {
        float mean = g_stats[tid] * (1.f / NN);
        float var  = g_stats[HD + tid] * (1.f / NN) - mean * mean;
        float inv  = rsqrtf(var + BN_EPS);
        float sc   = gamma[tid] * inv;
        s_sc[tid] = sc;
        s_sh[tid] = beta[tid] - mean * sc;
    }
    __syncthreads();
    int i = blockIdx.x * blockDim.x + tid;
    if (i >= NN * (HD / 4)) return;
    int c0 = (i & 15) * 4;
    float4 y  = reinterpret_cast<const float4*>(g_y)[i];
    float4 h  = reinterpret_cast<const float4*>(g_h)[i];
    float4 sc = *reinterpret_cast<const float4*>(&s_sc[c0]);
    float4 sh = *reinterpret_cast<const float4*>(&s_sh[c0]);
    float4 o;
    o.x = fmaxf(fmaf(y.x, sc.x, sh.x), 0.f) + h.x;
    o.y = fmaxf(fmaf(y.y, sc.y, sh.y), 0.f) + h.y;
    o.z = fmaxf(fmaf(y.z, sc.z, sh.z), 0.f) + h.z;
    o.w = fmaxf(fmaf(y.w, sc.w, sh.w), 0.f) + h.w;
    float4* dst = last ? reinterpret_cast<float4*>(out_final)
                       : reinterpret_cast<float4*>(g_h);
    dst[i] = o;
}

// ---------------- launch ----------------------------------------------------

extern "C" void kernel_launch(void* const* d_in, const int* in_sizes, int n_in,
                              void* d_out, int out_size) {
    const float* node_feat = (const float*)d_in[0];
    const float* edge_feat = (const float*)d_in[1];
    const int*   src       = (const int*)d_in[2];
    const int*   dst       = (const int*)d_in[3];
    const float* We        = (const float*)d_in[4];
    const float* be        = (const float*)d_in[5];
    const float* W1        = (const float*)d_in[6];
    const float* b1        = (const float*)d_in[7];
    const float* W2        = (const float*)d_in[8];
    const float* b2        = (const float*)d_in[9];
    const float* gamma     = (const float*)d_in[10];
    const float* beta      = (const float*)d_in[11];
    float* out = (float*)d_out;

    cudaFuncSetAttribute(k2_mlp, cudaFuncAttributeMaxDynamicSharedMemorySize, K2_SMEM);

    const int T = 256;
    k_hist<<<(NE + T - 1) / T, T>>>(dst);
    k_scan1<<<NCHUNKS, 512>>>();
    k_scatter<<<(NE + T - 1) / T, T>>>(src, dst,
                                       reinterpret_cast<const float4*>(edge_feat),
                                       reinterpret_cast<const float4*>(node_feat));

    for (int l = 0; l < 4; ++l) {
        k1_gather<<<NN / 2, 64>>>(We, be);
        k2_mlp<<<(NN + 63) / 64, 256, K2_SMEM>>>(W1 + l * HD * HD, b1 + l * HD,
                                                 W2 + l * HD * HD, b2 + l * HD);
        k4_post<<<(NN * 16 + T - 1) / T, T>>>(gamma + l * HD, beta + l * HD,
                                              out, l == 3 ? 1 : 0);
    }
}

// round 13
// speedup vs baseline: 1.0260x; 1.0194x over previous
#include <cuda_runtime.h>

#define NN 100000
#define NE 1600000
#define HD 64
#define BN_EPS 1e-5f
#define NCHUNKS 25   // ceil(NN/4096)

// ---------------- scratch (device globals; no runtime allocation) ----------
static __device__ __align__(16) float g_h[NN * HD];   // running node features
static __device__ __align__(16) float g_z[NN * HD];   // h + aggregation
static __device__ __align__(16) float g_y[NN * HD];   // MLP output (pre-BN)
static __device__ int    g_srcs[NE];                  // src sorted by dst (CSR)
static __device__ float4 g_ef[NE];                    // edge features sorted by dst
static __device__ int    g_deg[NN];                   // zero at entry (invariant)
static __device__ int    g_wcur[NN];                  // zero at entry (invariant)
static __device__ int    g_rowloc[NN];                // chunk-local prefix
static __device__ int    g_rowptr[NN + 1];            // final CSR rowptr
static __device__ int    g_part[32];                  // per-chunk edge totals
static __device__ float  g_stats[2 * HD];             // per-channel sum / sumsq

typedef unsigned long long u64;

__device__ __forceinline__ u64 pk2(float x, float y) {
    u64 r; asm("mov.b64 %0,{%1,%2};" : "=l"(r) : "f"(x), "f"(y)); return r;
}
__device__ __forceinline__ float2 upk2(u64 a) {
    float2 r; asm("mov.b64 {%0,%1},%2;" : "=f"(r.x), "=f"(r.y) : "l"(a)); return r;
}
__device__ __forceinline__ u64 ffma2(u64 a, u64 b, u64 c) {
    u64 d; asm("fma.rn.f32x2 %0,%1,%2,%3;" : "=l"(d) : "l"(a), "l"(b), "l"(c)); return d;
}

// ---------------- preprocessing (3 launches) --------------------------------

__global__ void k_hist(const int* __restrict__ dst) {
    int i = blockIdx.x * blockDim.x + threadIdx.x;
    if (i < NE) atomicAdd(&g_deg[dst[i]], 1);
}

__global__ void __launch_bounds__(512, 1) k_scan1() {
    __shared__ int s[512];
    int tid = threadIdx.x;
    int base = blockIdx.x * 4096 + tid * 8;
    int items[8]; int t = 0;
#pragma unroll
    for (int j = 0; j < 8; ++j) {
        int idx = base + j;
        int v = 0;
        if (idx < NN) { v = g_deg[idx]; g_deg[idx] = 0; g_wcur[idx] = 0; }
        items[j] = v; t += v;
    }
    s[tid] = t;
    __syncthreads();
    for (int off = 1; off < 512; off <<= 1) {
        int x = (tid >= off) ? s[tid - off] : 0;
        __syncthreads();
        s[tid] += x;
        __syncthreads();
    }
    int run = s[tid] - t;
#pragma unroll
    for (int j = 0; j < 8; ++j) {
        int idx = base + j;
        if (idx < NN) g_rowloc[idx] = run;
        run += items[j];
    }
    if (tid == 511) g_part[blockIdx.x] = s[511];
}

__global__ void k_scatter(const int* __restrict__ src, const int* __restrict__ dst,
                          const float4* __restrict__ ef, const float4* __restrict__ nf) {
    __shared__ int s_off[32];
    if (threadIdx.x < 32) {
        int orig = (threadIdx.x < NCHUNKS) ? g_part[threadIdx.x] : 0;
        int v = orig;
        for (int off = 1; off < 32; off <<= 1) {
            int x = __shfl_up_sync(0xffffffffu, v, off);
            if ((threadIdx.x & 31) >= off) v += x;
        }
        s_off[threadIdx.x] = v - orig;  // exclusive prefix
    }
    __syncthreads();
    int gt = blockIdx.x * blockDim.x + threadIdx.x;
    int gsz = gridDim.x * blockDim.x;
    for (int i = gt; i < NE; i += gsz) {
        int d = dst[i];
        int pos = g_rowloc[d] + s_off[d >> 12] + atomicAdd(&g_wcur[d], 1);
        g_srcs[pos] = src[i];
        g_ef[pos]   = ef[i];
    }
    for (int i = gt; i < NN; i += gsz)
        g_rowptr[i] = g_rowloc[i] + s_off[i >> 12];
    if (gt == 0) g_rowptr[NN] = NE;
    for (int i = gt; i < NN * (HD / 4); i += gsz)
        reinterpret_cast<float4*>(g_h)[i] = nf[i];
}

// ---------------- per-layer kernels ----------------------------------------

// K1 (#4 -> ncu capture slot): one warp per node, lane owns channels
// (2*lane, 2*lane+1). Edge metadata batch-loaded coalesced into SMEM staging
// (6 wavefronts / 32 edges), then per-edge 2 broadcast LDS (N=1, free)
// instead of 5 SHFL (R8) or 2 uniform-LDG wavefronts (R7).
__global__ void __launch_bounds__(64) k1_gather(const float* __restrict__ We,
                                                const float* __restrict__ be) {
    __shared__ int    s_src[2][32];
    __shared__ __align__(16) float4 s_f[2][32];
    if (blockIdx.x == 0 && threadIdx.x < HD) {
        g_stats[threadIdx.x] = 0.f;
        g_stats[HD + threadIdx.x] = 0.f;
    }
    int wid  = threadIdx.x >> 5;
    int lane = threadIdx.x & 31;
    int n    = blockIdx.x * 2 + wid;
    if (n >= NN) return;

    const float2* We2 = reinterpret_cast<const float2*>(We);
    const float2* be2 = reinterpret_cast<const float2*>(be);
    const float2* h2  = reinterpret_cast<const float2*>(g_h);
    float2 w0 = We2[0 * 32 + lane];
    float2 w1 = We2[1 * 32 + lane];
    float2 w2 = We2[2 * 32 + lane];
    float2 w3 = We2[3 * 32 + lane];
    float2 bb = be2[lane];

    int beg = g_rowptr[n], end = g_rowptr[n + 1];
    float2 a0 = h2[n * 32 + lane];
    float acc0 = a0.x, acc1 = a0.y;

    int j = beg;
    while (j < end) {
        int cnt = end - j;
        if (cnt > 32) cnt = 32;
        if (lane < cnt) {
            s_src[wid][lane] = g_srcs[j + lane];
            s_f[wid][lane]   = g_ef[j + lane];
        }
        __syncwarp();
#pragma unroll 4
        for (int t = 0; t < cnt; ++t) {
            int    s = s_src[wid][t];
            float4 f = s_f[wid][t];
            float2 v = h2[s * 32 + lane];
            float e0 = fmaf(f.x, w0.x, fmaf(f.y, w1.x, fmaf(f.z, w2.x, fmaf(f.w, w3.x, bb.x))));
            float e1 = fmaf(f.x, w0.y, fmaf(f.y, w1.y, fmaf(f.z, w2.y, fmaf(f.w, w3.y, bb.y))));
            acc0 += fmaxf(v.x + e0, 0.f);
            acc1 += fmaxf(v.y + e1, 0.f);
        }
        __syncwarp();
        j += cnt;
    }
    reinterpret_cast<float2*>(g_z)[n * 32 + lane] = make_float2(acc0, acc1);
}

// K2: fused y = relu(z@W1+b1)@W2+b2 over a 64-row tile, plus BN batch stats.
// A rows pair NATURALLY in smem (one LDS.128 = two u64 row-pairs, no MOVs);
// W splatted in-register (4 MOVs/iter).
#define K2_SMEM (64 * 68 * 4 + 64 * 64 * 4 + 128 * 4)
__global__ void __launch_bounds__(256, 6) k2_mlp(
    const float* __restrict__ W1, const float* __restrict__ b1,
    const float* __restrict__ W2, const float* __restrict__ b2) {
    extern __shared__ char smem_raw[];
    float* sA   = reinterpret_cast<float*>(smem_raw);            // [64][68]
    float* sW   = reinterpret_cast<float*>(smem_raw + 64 * 68 * 4);
    float* ssum = sW + 64 * 64;
    float* ssq  = ssum + 64;

    int tid = threadIdx.x;
    int rb  = blockIdx.x * 64;
    if (tid < 64) { ssum[tid] = 0.f; ssq[tid] = 0.f; }

    int tx = tid & 15, ty = tid >> 4;
    int c0 = tx * 4, r0 = ty * 4;

    // load z tile transposed: sA[k][r] = z[r][k]
    for (int itr = 0; itr < 4; ++itr) {
        int r = ty + itr * 16;
        float4 v = make_float4(0.f, 0.f, 0.f, 0.f);
        if (rb + r < NN) v = *reinterpret_cast<const float4*>(g_z + (rb + r) * 64 + c0);
        sA[(c0 + 0) * 68 + r] = v.x;
        sA[(c0 + 1) * 68 + r] = v.y;
        sA[(c0 + 2) * 68 + r] = v.z;
        sA[(c0 + 3) * 68 + r] = v.w;
    }
    for (int itr = 0; itr < 4; ++itr) {
        int idx = tid + itr * 256;
        reinterpret_cast<float4*>(sW)[idx] = __ldg(reinterpret_cast<const float4*>(W1) + idx);
    }
    __syncthreads();

    // ---- GEMM1: q[rp][c] pairs rows (r0,r0+1)/(r0+2,r0+3) against col c ----
    u64 q0 = 0, q1 = 0, q2 = 0, q3 = 0, q4 = 0, q5 = 0, q6 = 0, q7 = 0;
#pragma unroll 8
    for (int k = 0; k < 64; ++k) {
        ulonglong2 p = *reinterpret_cast<ulonglong2*>(&sA[k * 68 + r0]);  // rows r0..r0+3
        float4 wv    = *reinterpret_cast<float4*>(&sW[k * 64 + c0]);
        u64 ws0 = pk2(wv.x, wv.x), ws1 = pk2(wv.y, wv.y);
        u64 ws2 = pk2(wv.z, wv.z), ws3 = pk2(wv.w, wv.w);
        q0 = ffma2(p.x, ws0, q0); q1 = ffma2(p.x, ws1, q1);
        q2 = ffma2(p.x, ws2, q2); q3 = ffma2(p.x, ws3, q3);
        q4 = ffma2(p.y, ws0, q4); q5 = ffma2(p.y, ws1, q5);
        q6 = ffma2(p.y, ws2, q6); q7 = ffma2(p.y, ws3, q7);
    }
    float4 bb1 = __ldg(reinterpret_cast<const float4*>(b1 + c0));
    float tt[4][4];
    { float2 u = upk2(q0); tt[0][0] = u.x; tt[1][0] = u.y; }
    { float2 u = upk2(q1); tt[0][1] = u.x; tt[1][1] = u.y; }
    { float2 u = upk2(q2); tt[0][2] = u.x; tt[1][2] = u.y; }
    { float2 u = upk2(q3); tt[0][3] = u.x; tt[1][3] = u.y; }
    { float2 u = upk2(q4); tt[2][0] = u.x; tt[3][0] = u.y; }
    { float2 u = upk2(q5); tt[2][1] = u.x; tt[3][1] = u.y; }
    { float2 u = upk2(q6); tt[2][2] = u.x; tt[3][2] = u.y; }
    { float2 u = upk2(q7); tt[2][3] = u.x; tt[3][3] = u.y; }
#pragma unroll
    for (int i = 0; i < 4; ++i) {
        tt[i][0] = fmaxf(tt[i][0] + bb1.x, 0.f);
        tt[i][1] = fmaxf(tt[i][1] + bb1.y, 0.f);
        tt[i][2] = fmaxf(tt[i][2] + bb1.z, 0.f);
        tt[i][3] = fmaxf(tt[i][3] + bb1.w, 0.f);
    }
    __syncthreads();  // everyone done reading sA / sW

    // store t transposed (k index = channel c); reload sW with W2
#pragma unroll
    for (int i = 0; i < 4; ++i)
#pragma unroll
        for (int j = 0; j < 4; ++j)
            sA[(c0 + j) * 68 + (r0 + i)] = tt[i][j];
    for (int itr = 0; itr < 4; ++itr) {
        int idx = tid + itr * 256;
        reinterpret_cast<float4*>(sW)[idx] = __ldg(reinterpret_cast<const float4*>(W2) + idx);
    }
    __syncthreads();

    // ---- GEMM2 ----
    q0 = q1 = q2 = q3 = q4 = q5 = q6 = q7 = 0;
#pragma unroll 8
    for (int k = 0; k < 64; ++k) {
        ulonglong2 p = *reinterpret_cast<ulonglong2*>(&sA[k * 68 + r0]);
        float4 wv    = *reinterpret_cast<float4*>(&sW[k * 64 + c0]);
        u64 ws0 = pk2(wv.x, wv.x), ws1 = pk2(wv.y, wv.y);
        u64 ws2 = pk2(wv.z, wv.z), ws3 = pk2(wv.w, wv.w);
        q0 = ffma2(p.x, ws0, q0); q1 = ffma2(p.x, ws1, q1);
        q2 = ffma2(p.x, ws2, q2); q3 = ffma2(p.x, ws3, q3);
        q4 = ffma2(p.y, ws0, q4); q5 = ffma2(p.y, ws1, q5);
        q6 = ffma2(p.y, ws2, q6); q7 = ffma2(p.y, ws3, q7);
    }
    float4 bb2 = __ldg(reinterpret_cast<const float4*>(b2 + c0));
    float yy[4][4];
    { float2 u = upk2(q0); yy[0][0] = u.x + bb2.x; yy[1][0] = u.y + bb2.x; }
    { float2 u = upk2(q1); yy[0][1] = u.x + bb2.y; yy[1][1] = u.y + bb2.y; }
    { float2 u = upk2(q2); yy[0][2] = u.x + bb2.z; yy[1][2] = u.y + bb2.z; }
    { float2 u = upk2(q3); yy[0][3] = u.x + bb2.w; yy[1][3] = u.y + bb2.w; }
    { float2 u = upk2(q4); yy[2][0] = u.x + bb2.x; yy[3][0] = u.y + bb2.x; }
    { float2 u = upk2(q5); yy[2][1] = u.x + bb2.y; yy[3][1] = u.y + bb2.y; }
    { float2 u = upk2(q6); yy[2][2] = u.x + bb2.z; yy[3][2] = u.y + bb2.z; }
    { float2 u = upk2(q7); yy[2][3] = u.x + bb2.w; yy[3][3] = u.y + bb2.w; }

    // write y + accumulate stats
#pragma unroll
    for (int i = 0; i < 4; ++i) {
        int r = rb + r0 + i;
        if (r < NN) {
            float4 v = make_float4(yy[i][0], yy[i][1], yy[i][2], yy[i][3]);
            *reinterpret_cast<float4*>(g_y + r * 64 + c0) = v;
        }
    }
#pragma unroll
    for (int j = 0; j < 4; ++j) {
        float sj = 0.f, qj = 0.f;
#pragma unroll
        for (int i = 0; i < 4; ++i) {
            if (rb + r0 + i < NN) { sj += yy[i][j]; qj += yy[i][j] * yy[i][j]; }
        }
        atomicAdd(&ssum[c0 + j], sj);
        atomicAdd(&ssq[c0 + j], qj);
    }
    __syncthreads();
    if (tid < 64) {
        atomicAdd(&g_stats[tid], ssum[tid]);
        atomicAdd(&g_stats[64 + tid], ssq[tid]);
    }
}

// K4: BN finalize (per-block redundant) + h = relu(y*scale+shift) + h
__global__ void k4_post(const float* __restrict__ gamma, const float* __restrict__ beta,
                        float* __restrict__ out_final, int last) {
    __shared__ float s_sc[HD], s_sh[HD];
    int tid = threadIdx.x;
    if (tid < HD) {
        float mean = g_stats[tid] * (1.f / NN);
        float var  = g_stats[HD + tid] * (1.f / NN) - mean * mean;
        float inv  = rsqrtf(var + BN_EPS);
        float sc   = gamma[tid] * inv;
        s_sc[tid] = sc;
        s_sh[tid] = beta[tid] - mean * sc;
    }
    __syncthreads();
    int i = blockIdx.x * blockDim.x + tid;
    if (i >= NN * (HD / 4)) return;
    int c0 = (i & 15) * 4;
    float4 y  = reinterpret_cast<const float4*>(g_y)[i];
    float4 h  = reinterpret_cast<const float4*>(g_h)[i];
    float4 sc = *reinterpret_cast<const float4*>(&s_sc[c0]);
    float4 sh = *reinterpret_cast<const float4*>(&s_sh[c0]);
    float4 o;
    o.x = fmaxf(fmaf(y.x, sc.x, sh.x), 0.f) + h.x;
    o.y = fmaxf(fmaf(y.y, sc.y, sh.y), 0.f) + h.y;
    o.z = fmaxf(fmaf(y.z, sc.z, sh.z), 0.f) + h.z;
    o.w = fmaxf(fmaf(y.w, sc.w, sh.w), 0.f) + h.w;
    float4* dst = last ? reinterpret_cast<float4*>(out_final)
                       : reinterpret_cast<float4*>(g_h);
    dst[i] = o;
}

// ---------------- launch ----------------------------------------------------

extern "C" void kernel_launch(void* const* d_in, const int* in_sizes, int n_in,
                              void* d_out, int out_size) {
    const float* node_feat = (const float*)d_in[0];
    const float* edge_feat = (const float*)d_in[1];
    const int*   src       = (const int*)d_in[2];
    const int*   dst       = (const int*)d_in[3];
    const float* We        = (const float*)d_in[4];
    const float* be        = (const float*)d_in[5];
    const float* W1        = (const float*)d_in[6];
    const float* b1        = (const float*)d_in[7];
    const float* W2        = (const float*)d_in[8];
    const float* b2        = (const float*)d_in[9];
    const float* gamma     = (const float*)d_in[10];
    const float* beta      = (const float*)d_in[11];
    float* out = (float*)d_out;

    cudaFuncSetAttribute(k2_mlp, cudaFuncAttributeMaxDynamicSharedMemorySize, K2_SMEM);

    const int T = 256;
    k_hist<<<(NE + T - 1) / T, T>>>(dst);
    k_scan1<<<NCHUNKS, 512>>>();
    k_scatter<<<(NE + T - 1) / T, T>>>(src, dst,
                                       reinterpret_cast<const float4*>(edge_feat),
                                       reinterpret_cast<const float4*>(node_feat));

    for (int l = 0; l < 4; ++l) {
        k1_gather<<<NN / 2, 64>>>(We, be);
        k2_mlp<<<(NN + 63) / 64, 256, K2_SMEM>>>(W1 + l * HD * HD, b1 + l * HD,
                                                 W2 + l * HD * HD, b2 + l * HD);
        k4_post<<<(NN * 16 + T - 1) / T, T>>>(gamma + l * HD, beta + l * HD,
                                              out, l == 3 ? 1 : 0);
    }
}

// round 14
// speedup vs baseline: 1.0441x; 1.0176x over previous
#include <cuda_runtime.h>

#define NN 100000
#define NE 1600000
#define HD 64
#define BN_EPS 1e-5f
#define NCHUNKS 25   // ceil(NN/4096)

// ---------------- scratch (device globals; no runtime allocation) ----------
static __device__ __align__(16) float g_h[NN * HD];   // running node features
static __device__ __align__(16) float g_z[NN * HD];   // h + aggregation
static __device__ __align__(16) float g_y[NN * HD];   // MLP output (pre-BN)
static __device__ int    g_srcs[NE];                  // src sorted by dst (CSR)
static __device__ float4 g_ef[NE];                    // edge features sorted by dst
static __device__ int    g_deg[NN];                   // zero at entry (invariant)
static __device__ int    g_wcur[NN];                  // zero at entry (invariant)
static __device__ int    g_rowloc[NN];                // chunk-local prefix
static __device__ int    g_rowptr[NN + 1];            // final CSR rowptr
static __device__ int    g_part[32];                  // per-chunk edge totals
static __device__ float  g_stats[2 * HD];             // per-channel sum / sumsq

typedef unsigned long long u64;

__device__ __forceinline__ u64 pk2(float x, float y) {
    u64 r; asm("mov.b64 %0,{%1,%2};" : "=l"(r) : "f"(x), "f"(y)); return r;
}
__device__ __forceinline__ float2 upk2(u64 a) {
    float2 r; asm("mov.b64 {%0,%1},%2;" : "=f"(r.x), "=f"(r.y) : "l"(a)); return r;
}
__device__ __forceinline__ u64 ffma2(u64 a, u64 b, u64 c) {
    u64 d; asm("fma.rn.f32x2 %0,%1,%2,%3;" : "=l"(d) : "l"(a), "l"(b), "l"(c)); return d;
}

// ---------------- preprocessing (3 launches) --------------------------------

__global__ void k_hist(const int* __restrict__ dst) {
    int i = blockIdx.x * blockDim.x + threadIdx.x;
    if (i < NE) atomicAdd(&g_deg[dst[i]], 1);
}

__global__ void __launch_bounds__(512, 1) k_scan1() {
    __shared__ int s[512];
    int tid = threadIdx.x;
    int base = blockIdx.x * 4096 + tid * 8;
    int items[8]; int t = 0;
#pragma unroll
    for (int j = 0; j < 8; ++j) {
        int idx = base + j;
        int v = 0;
        if (idx < NN) { v = g_deg[idx]; g_deg[idx] = 0; g_wcur[idx] = 0; }
        items[j] = v; t += v;
    }
    s[tid] = t;
    __syncthreads();
    for (int off = 1; off < 512; off <<= 1) {
        int x = (tid >= off) ? s[tid - off] : 0;
        __syncthreads();
        s[tid] += x;
        __syncthreads();
    }
    int run = s[tid] - t;
#pragma unroll
    for (int j = 0; j < 8; ++j) {
        int idx = base + j;
        if (idx < NN) g_rowloc[idx] = run;
        run += items[j];
    }
    if (tid == 511) g_part[blockIdx.x] = s[511];
}

__global__ void k_scatter(const int* __restrict__ src, const int* __restrict__ dst,
                          const float4* __restrict__ ef, const float4* __restrict__ nf) {
    __shared__ int s_off[32];
    if (threadIdx.x < 32) {
        int orig = (threadIdx.x < NCHUNKS) ? g_part[threadIdx.x] : 0;
        int v = orig;
        for (int off = 1; off < 32; off <<= 1) {
            int x = __shfl_up_sync(0xffffffffu, v, off);
            if ((threadIdx.x & 31) >= off) v += x;
        }
        s_off[threadIdx.x] = v - orig;  // exclusive prefix
    }
    __syncthreads();
    int gt = blockIdx.x * blockDim.x + threadIdx.x;
    int gsz = gridDim.x * blockDim.x;
    for (int i = gt; i < NE; i += gsz) {
        int d = dst[i];
        int pos = g_rowloc[d] + s_off[d >> 12] + atomicAdd(&g_wcur[d], 1);
        g_srcs[pos] = src[i];
        g_ef[pos]   = ef[i];
    }
    for (int i = gt; i < NN; i += gsz)
        g_rowptr[i] = g_rowloc[i] + s_off[i >> 12];
    if (gt == 0) g_rowptr[NN] = NE;
    for (int i = gt; i < NN * (HD / 4); i += gsz)
        reinterpret_cast<float4*>(g_h)[i] = nf[i];
}

// ---------------- per-layer kernels ----------------------------------------

// K1 (#4 -> ncu capture slot): one warp per node, lane owns channels
// (2*lane, 2*lane+1). Edge metadata batch-loaded coalesced into SMEM staging,
// per-edge 2 broadcast LDS. __launch_bounds__(64, 32) caps regs at 32 so the
// RF allows 32 resident blocks (64 warps/SM) -> occupancy toward 100%.
__global__ void __launch_bounds__(64, 32) k1_gather(const float* __restrict__ We,
                                                    const float* __restrict__ be) {
    __shared__ int    s_src[2][32];
    __shared__ __align__(16) float4 s_f[2][32];
    if (blockIdx.x == 0 && threadIdx.x < HD) {
        g_stats[threadIdx.x] = 0.f;
        g_stats[HD + threadIdx.x] = 0.f;
    }
    int wid  = threadIdx.x >> 5;
    int lane = threadIdx.x & 31;
    int n    = blockIdx.x * 2 + wid;
    if (n >= NN) return;

    const float2* We2 = reinterpret_cast<const float2*>(We);
    const float2* be2 = reinterpret_cast<const float2*>(be);
    const float2* h2  = reinterpret_cast<const float2*>(g_h);
    float2 w0 = We2[0 * 32 + lane];
    float2 w1 = We2[1 * 32 + lane];
    float2 w2 = We2[2 * 32 + lane];
    float2 w3 = We2[3 * 32 + lane];
    float2 bb = be2[lane];

    int beg = g_rowptr[n], end = g_rowptr[n + 1];
    float2 a0 = h2[n * 32 + lane];
    float acc0 = a0.x, acc1 = a0.y;

    int j = beg;
    while (j < end) {
        int cnt = end - j;
        if (cnt > 32) cnt = 32;
        if (lane < cnt) {
            s_src[wid][lane] = g_srcs[j + lane];
            s_f[wid][lane]   = g_ef[j + lane];
        }
        __syncwarp();
#pragma unroll 4
        for (int t = 0; t < cnt; ++t) {
            int    s = s_src[wid][t];
            float4 f = s_f[wid][t];
            float2 v = h2[s * 32 + lane];
            float e0 = fmaf(f.x, w0.x, fmaf(f.y, w1.x, fmaf(f.z, w2.x, fmaf(f.w, w3.x, bb.x))));
            float e1 = fmaf(f.x, w0.y, fmaf(f.y, w1.y, fmaf(f.z, w2.y, fmaf(f.w, w3.y, bb.y))));
            acc0 += fmaxf(v.x + e0, 0.f);
            acc1 += fmaxf(v.y + e1, 0.f);
        }
        __syncwarp();
        j += cnt;
    }
    reinterpret_cast<float2*>(g_z)[n * 32 + lane] = make_float2(acc0, acc1);
}

// K2: fused y = relu(z@W1+b1)@W2+b2 over a 64-row tile, plus BN batch stats.
// A rows pair NATURALLY in smem (one LDS.128 = two u64 row-pairs, no MOVs);
// W splatted in-register (4 MOVs/iter).
#define K2_SMEM (64 * 68 * 4 + 64 * 64 * 4 + 128 * 4)
__global__ void __launch_bounds__(256, 6) k2_mlp(
    const float* __restrict__ W1, const float* __restrict__ b1,
    const float* __restrict__ W2, const float* __restrict__ b2) {
    extern __shared__ char smem_raw[];
    float* sA   = reinterpret_cast<float*>(smem_raw);            // [64][68]
    float* sW   = reinterpret_cast<float*>(smem_raw + 64 * 68 * 4);
    float* ssum = sW + 64 * 64;
    float* ssq  = ssum + 64;

    int tid = threadIdx.x;
    int rb  = blockIdx.x * 64;
    if (tid < 64) { ssum[tid] = 0.f; ssq[tid] = 0.f; }

    int tx = tid & 15, ty = tid >> 4;
    int c0 = tx * 4, r0 = ty * 4;

    // load z tile transposed: sA[k][r] = z[r][k]
    for (int itr = 0; itr < 4; ++itr) {
        int r = ty + itr * 16;
        float4 v = make_float4(0.f, 0.f, 0.f, 0.f);
        if (rb + r < NN) v = *reinterpret_cast<const float4*>(g_z + (rb + r) * 64 + c0);
        sA[(c0 + 0) * 68 + r] = v.x;
        sA[(c0 + 1) * 68 + r] = v.y;
        sA[(c0 + 2) * 68 + r] = v.z;
        sA[(c0 + 3) * 68 + r] = v.w;
    }
    for (int itr = 0; itr < 4; ++itr) {
        int idx = tid + itr * 256;
        reinterpret_cast<float4*>(sW)[idx] = __ldg(reinterpret_cast<const float4*>(W1) + idx);
    }
    __syncthreads();

    // ---- GEMM1: q[rp][c] pairs rows (r0,r0+1)/(r0+2,r0+3) against col c ----
    u64 q0 = 0, q1 = 0, q2 = 0, q3 = 0, q4 = 0, q5 = 0, q6 = 0, q7 = 0;
#pragma unroll 8
    for (int k = 0; k < 64; ++k) {
        ulonglong2 p = *reinterpret_cast<ulonglong2*>(&sA[k * 68 + r0]);  // rows r0..r0+3
        float4 wv    = *reinterpret_cast<float4*>(&sW[k * 64 + c0]);
        u64 ws0 = pk2(wv.x, wv.x), ws1 = pk2(wv.y, wv.y);
        u64 ws2 = pk2(wv.z, wv.z), ws3 = pk2(wv.w, wv.w);
        q0 = ffma2(p.x, ws0, q0); q1 = ffma2(p.x, ws1, q1);
        q2 = ffma2(p.x, ws2, q2); q3 = ffma2(p.x, ws3, q3);
        q4 = ffma2(p.y, ws0, q4); q5 = ffma2(p.y, ws1, q5);
        q6 = ffma2(p.y, ws2, q6); q7 = ffma2(p.y, ws3, q7);
    }
    float4 bb1 = __ldg(reinterpret_cast<const float4*>(b1 + c0));
    float tt[4][4];
    { float2 u = upk2(q0); tt[0][0] = u.x; tt[1][0] = u.y; }
    { float2 u = upk2(q1); tt[0][1] = u.x; tt[1][1] = u.y; }
    { float2 u = upk2(q2); tt[0][2] = u.x; tt[1][2] = u.y; }
    { float2 u = upk2(q3); tt[0][3] = u.x; tt[1][3] = u.y; }
    { float2 u = upk2(q4); tt[2][0] = u.x; tt[3][0] = u.y; }
    { float2 u = upk2(q5); tt[2][1] = u.x; tt[3][1] = u.y; }
    { float2 u = upk2(q6); tt[2][2] = u.x; tt[3][2] = u.y; }
    { float2 u = upk2(q7); tt[2][3] = u.x; tt[3][3] = u.y; }
#pragma unroll
    for (int i = 0; i < 4; ++i) {
        tt[i][0] = fmaxf(tt[i][0] + bb1.x, 0.f);
        tt[i][1] = fmaxf(tt[i][1] + bb1.y, 0.f);
        tt[i][2] = fmaxf(tt[i][2] + bb1.z, 0.f);
        tt[i][3] = fmaxf(tt[i][3] + bb1.w, 0.f);
    }
    __syncthreads();  // everyone done reading sA / sW

    // store t transposed (k index = channel c); reload sW with W2
#pragma unroll
    for (int i = 0; i < 4; ++i)
#pragma unroll
        for (int j = 0; j < 4; ++j)
            sA[(c0 + j) * 68 + (r0 + i)] = tt[i][j];
    for (int itr = 0; itr < 4; ++itr) {
        int idx = tid + itr * 256;
        reinterpret_cast<float4*>(sW)[idx] = __ldg(reinterpret_cast<const float4*>(W2) + idx);
    }
    __syncthreads();

    // ---- GEMM2 ----
    q0 = q1 = q2 = q3 = q4 = q5 = q6 = q7 = 0;
#pragma unroll 8
    for (int k = 0; k < 64; ++k) {
        ulonglong2 p = *reinterpret_cast<ulonglong2*>(&sA[k * 68 + r0]);
        float4 wv    = *reinterpret_cast<float4*>(&sW[k * 64 + c0]);
        u64 ws0 = pk2(wv.x, wv.x), ws1 = pk2(wv.y, wv.y);
        u64 ws2 = pk2(wv.z, wv.z), ws3 = pk2(wv.w, wv.w);
        q0 = ffma2(p.x, ws0, q0); q1 = ffma2(p.x, ws1, q1);
        q2 = ffma2(p.x, ws2, q2); q3 = ffma2(p.x, ws3, q3);
        q4 = ffma2(p.y, ws0, q4); q5 = ffma2(p.y, ws1, q5);
        q6 = ffma2(p.y, ws2, q6); q7 = ffma2(p.y, ws3, q7);
    }
    float4 bb2 = __ldg(reinterpret_cast<const float4*>(b2 + c0));
    float yy[4][4];
    { float2 u = upk2(q0); yy[0][0] = u.x + bb2.x; yy[1][0] = u.y + bb2.x; }
    { float2 u = upk2(q1); yy[0][1] = u.x + bb2.y; yy[1][1] = u.y + bb2.y; }
    { float2 u = upk2(q2); yy[0][2] = u.x + bb2.z; yy[1][2] = u.y + bb2.z; }
    { float2 u = upk2(q3); yy[0][3] = u.x + bb2.w; yy[1][3] = u.y + bb2.w; }
    { float2 u = upk2(q4); yy[2][0] = u.x + bb2.x; yy[3][0] = u.y + bb2.x; }
    { float2 u = upk2(q5); yy[2][1] = u.x + bb2.y; yy[3][1] = u.y + bb2.y; }
    { float2 u = upk2(q6); yy[2][2] = u.x + bb2.z; yy[3][2] = u.y + bb2.z; }
    { float2 u = upk2(q7); yy[2][3] = u.x + bb2.w; yy[3][3] = u.y + bb2.w; }

    // write y + accumulate stats
#pragma unroll
    for (int i = 0; i < 4; ++i) {
        int r = rb + r0 + i;
        if (r < NN) {
            float4 v = make_float4(yy[i][0], yy[i][1], yy[i][2], yy[i][3]);
            *reinterpret_cast<float4*>(g_y + r * 64 + c0) = v;
        }
    }
#pragma unroll
    for (int j = 0; j < 4; ++j) {
        float sj = 0.f, qj = 0.f;
#pragma unroll
        for (int i = 0; i < 4; ++i) {
            if (rb + r0 + i < NN) { sj += yy[i][j]; qj += yy[i][j] * yy[i][j]; }
        }
        atomicAdd(&ssum[c0 + j], sj);
        atomicAdd(&ssq[c0 + j], qj);
    }
    __syncthreads();
    if (tid < 64) {
        atomicAdd(&g_stats[tid], ssum[tid]);
        atomicAdd(&g_stats[64 + tid], ssq[tid]);
    }
}

// K4: BN finalize (per-block redundant) + h = relu(y*scale+shift) + h
__global__ void k4_post(const float* __restrict__ gamma, const float* __restrict__ beta,
                        float* __restrict__ out_final, int last) {
    __shared__ float s_sc[HD], s_sh[HD];
    int tid = threadIdx.x;
    if (tid < HD) {
        float mean = g_stats[tid] * (1.f / NN);
        float var  = g_stats[HD + tid] * (1.f / NN) - mean * mean;
        float inv  = rsqrtf(var + BN_EPS);
        float sc   = gamma[tid] * inv;
        s_sc[tid] = sc;
        s_sh[tid] = beta[tid] - mean * sc;
    }
    __syncthreads();
    int i = blockIdx.x * blockDim.x + tid;
    if (i >= NN * (HD / 4)) return;
    int c0 = (i & 15) * 4;
    float4 y  = reinterpret_cast<const float4*>(g_y)[i];
    float4 h  = reinterpret_cast<const float4*>(g_h)[i];
    float4 sc = *reinterpret_cast<const float4*>(&s_sc[c0]);
    float4 sh = *reinterpret_cast<const float4*>(&s_sh[c0]);
    float4 o;
    o.x = fmaxf(fmaf(y.x, sc.x, sh.x), 0.f) + h.x;
    o.y = fmaxf(fmaf(y.y, sc.y, sh.y), 0.f) + h.y;
    o.z = fmaxf(fmaf(y.z, sc.z, sh.z), 0.f) + h.z;
    o.w = fmaxf(fmaf(y.w, sc.w, sh.w), 0.f) + h.w;
    float4* dst = last ? reinterpret_cast<float4*>(out_final)
                       : reinterpret_cast<float4*>(g_h);
    dst[i] = o;
}

// ---------------- launch ----------------------------------------------------

extern "C" void kernel_launch(void* const* d_in, const int* in_sizes, int n_in,
                              void* d_out, int out_size) {
    const float* node_feat = (const float*)d_in[0];
    const float* edge_feat = (const float*)d_in[1];
    const int*   src       = (const int*)d_in[2];
    const int*   dst       = (const int*)d_in[3];
    const float* We        = (const float*)d_in[4];
    const float* be        = (const float*)d_in[5];
    const float* W1        = (const float*)d_in[6];
    const float* b1        = (const float*)d_in[7];
    const float* W2        = (const float*)d_in[8];
    const float* b2        = (const float*)d_in[9];
    const float* gamma     = (const float*)d_in[10];
    const float* beta      = (const float*)d_in[11];
    float* out = (float*)d_out;

    cudaFuncSetAttribute(k2_mlp, cudaFuncAttributeMaxDynamicSharedMemorySize, K2_SMEM);

    const int T = 256;
    k_hist<<<(NE + T - 1) / T, T>>>(dst);
    k_scan1<<<NCHUNKS, 512>>>();
    k_scatter<<<(NE + T - 1) / T, T>>>(src, dst,
                                       reinterpret_cast<const float4*>(edge_feat),
                                       reinterpret_cast<const float4*>(node_feat));

    for (int l = 0; l < 4; ++l) {
        k1_gather<<<NN / 2, 64>>>(We, be);
        k2_mlp<<<(NN + 63) / 64, 256, K2_SMEM>>>(W1 + l * HD * HD, b1 + l * HD,
                                                 W2 + l * HD * HD, b2 + l * HD);
        k4_post<<<(NN * 16 + T - 1) / T, T>>>(gamma + l * HD, beta + l * HD,
                                              out, l == 3 ? 1 : 0);
    }
}

// round 15
// speedup vs baseline: 1.0809x; 1.0353x over previous
#include <cuda_runtime.h>

#define NN 100000
#define NE 1600000
#define HD 64
#define BN_EPS 1e-5f
#define NCHUNKS 25   // ceil(NN/4096)

// ---------------- scratch (device globals; no runtime allocation) ----------
static __device__ __align__(16) float g_h[NN * HD];   // running node features
static __device__ __align__(16) float g_z[NN * HD];   // h + aggregation
static __device__ __align__(16) float g_y[NN * HD];   // MLP output (pre-BN)
static __device__ int    g_srcs[NE];                  // src sorted by dst (CSR)
static __device__ float4 g_ef[NE];                    // edge features sorted by dst
static __device__ int    g_deg[NN];                   // zero at entry (invariant)
static __device__ int    g_wcur[NN];                  // zero at entry (invariant)
static __device__ int    g_rowloc[NN];                // chunk-local prefix
static __device__ int    g_rowptr[NN + 1];            // final CSR rowptr
static __device__ int    g_part[32];                  // per-chunk edge totals
static __device__ float  g_stats[2 * HD];             // per-channel sum / sumsq

typedef unsigned long long u64;

__device__ __forceinline__ u64 pk2(float x, float y) {
    u64 r; asm("mov.b64 %0,{%1,%2};" : "=l"(r) : "f"(x), "f"(y)); return r;
}
__device__ __forceinline__ float2 upk2(u64 a) {
    float2 r; asm("mov.b64 {%0,%1},%2;" : "=f"(r.x), "=f"(r.y) : "l"(a)); return r;
}
__device__ __forceinline__ u64 ffma2(u64 a, u64 b, u64 c) {
    u64 d; asm("fma.rn.f32x2 %0,%1,%2,%3;" : "=l"(d) : "l"(a), "l"(b), "l"(c)); return d;
}
// XOR swizzle of 4-float column blocks within a 64-col row (16 blocks)
__device__ __forceinline__ int swz(int row, int blk) { return blk ^ ((row >> 2) & 15); }

// ---------------- preprocessing ---------------------------------------------

// dummy first launch so the ncu capture slot (#4) lands on k_scatter
__global__ void k_slot() { if (threadIdx.x == 1023) g_part[31] = g_part[31]; }

__global__ void k_hist(const int* __restrict__ dst) {
    int i = blockIdx.x * blockDim.x + threadIdx.x;
    if (i < NE) atomicAdd(&g_deg[dst[i]], 1);
}

__global__ void __launch_bounds__(512, 1) k_scan1() {
    __shared__ int s[512];
    int tid = threadIdx.x;
    int base = blockIdx.x * 4096 + tid * 8;
    int items[8]; int t = 0;
#pragma unroll
    for (int j = 0; j < 8; ++j) {
        int idx = base + j;
        int v = 0;
        if (idx < NN) { v = g_deg[idx]; g_deg[idx] = 0; g_wcur[idx] = 0; }
        items[j] = v; t += v;
    }
    s[tid] = t;
    __syncthreads();
    for (int off = 1; off < 512; off <<= 1) {
        int x = (tid >= off) ? s[tid - off] : 0;
        __syncthreads();
        s[tid] += x;
        __syncthreads();
    }
    int run = s[tid] - t;
#pragma unroll
    for (int j = 0; j < 8; ++j) {
        int idx = base + j;
        if (idx < NN) g_rowloc[idx] = run;
        run += items[j];
    }
    if (tid == 511) g_part[blockIdx.x] = s[511];
}

__global__ void k_scatter(const int* __restrict__ src, const int* __restrict__ dst,
                          const float4* __restrict__ ef, const float4* __restrict__ nf) {
    __shared__ int s_off[32];
    if (threadIdx.x < 32) {
        int orig = (threadIdx.x < NCHUNKS) ? g_part[threadIdx.x] : 0;
        int v = orig;
        for (int off = 1; off < 32; off <<= 1) {
            int x = __shfl_up_sync(0xffffffffu, v, off);
            if ((threadIdx.x & 31) >= off) v += x;
        }
        s_off[threadIdx.x] = v - orig;  // exclusive prefix
    }
    __syncthreads();
    int gt = blockIdx.x * blockDim.x + threadIdx.x;
    int gsz = gridDim.x * blockDim.x;
    for (int i = gt; i < NE; i += gsz) {
        int d = dst[i];
        int pos = g_rowloc[d] + s_off[d >> 12] + atomicAdd(&g_wcur[d], 1);
        g_srcs[pos] = src[i];
        g_ef[pos]   = ef[i];
    }
    for (int i = gt; i < NN; i += gsz)
        g_rowptr[i] = g_rowloc[i] + s_off[i >> 12];
    if (gt == 0) g_rowptr[NN] = NE;
    for (int i = gt; i < NN * (HD / 4); i += gsz)
        reinterpret_cast<float4*>(g_h)[i] = nf[i];
}

// ---------------- per-layer kernels ----------------------------------------

// K1: one warp per node, lane owns channels (2*lane, 2*lane+1). SMEM-staged
// edge metadata; 32-reg cap -> 32 resident blocks.
__global__ void __launch_bounds__(64, 32) k1_gather(const float* __restrict__ We,
                                                    const float* __restrict__ be) {
    __shared__ int    s_src[2][32];
    __shared__ __align__(16) float4 s_f[2][32];
    if (blockIdx.x == 0 && threadIdx.x < HD) {
        g_stats[threadIdx.x] = 0.f;
        g_stats[HD + threadIdx.x] = 0.f;
    }
    int wid  = threadIdx.x >> 5;
    int lane = threadIdx.x & 31;
    int n    = blockIdx.x * 2 + wid;
    if (n >= NN) return;

    const float2* We2 = reinterpret_cast<const float2*>(We);
    const float2* be2 = reinterpret_cast<const float2*>(be);
    const float2* h2  = reinterpret_cast<const float2*>(g_h);
    float2 w0 = We2[0 * 32 + lane];
    float2 w1 = We2[1 * 32 + lane];
    float2 w2 = We2[2 * 32 + lane];
    float2 w3 = We2[3 * 32 + lane];
    float2 bb = be2[lane];

    int beg = g_rowptr[n], end = g_rowptr[n + 1];
    float2 a0 = h2[n * 32 + lane];
    float acc0 = a0.x, acc1 = a0.y;

    int j = beg;
    while (j < end) {
        int cnt = end - j;
        if (cnt > 32) cnt = 32;
        if (lane < cnt) {
            s_src[wid][lane] = g_srcs[j + lane];
            s_f[wid][lane]   = g_ef[j + lane];
        }
        __syncwarp();
#pragma unroll 4
        for (int t = 0; t < cnt; ++t) {
            int    s = s_src[wid][t];
            float4 f = s_f[wid][t];
            float2 v = h2[s * 32 + lane];
            float e0 = fmaf(f.x, w0.x, fmaf(f.y, w1.x, fmaf(f.z, w2.x, fmaf(f.w, w3.x, bb.x))));
            float e1 = fmaf(f.x, w0.y, fmaf(f.y, w1.y, fmaf(f.z, w2.y, fmaf(f.w, w3.y, bb.y))));
            acc0 += fmaxf(v.x + e0, 0.f);
            acc1 += fmaxf(v.y + e1, 0.f);
        }
        __syncwarp();
        j += cnt;
    }
    reinterpret_cast<float2*>(g_z)[n * 32 + lane] = make_float2(acc0, acc1);
}

// K2: fused y = relu(z@W1+b1)@W2+b2 over a 64-row tile, plus BN batch stats.
// sA columns XOR-swizzled in 4-float blocks: transpose STS spreads over 16
// banks (was 8-way conflicted); GEMM LDS.128 reads stay broadcast-clean.
#define K2_SMEM (64 * 68 * 4 + 64 * 64 * 4 + 128 * 4)
__global__ void __launch_bounds__(256, 6) k2_mlp(
    const float* __restrict__ W1, const float* __restrict__ b1,
    const float* __restrict__ W2, const float* __restrict__ b2) {
    extern __shared__ char smem_raw[];
    float* sA   = reinterpret_cast<float*>(smem_raw);            // [64][68] swizzled
    float* sW   = reinterpret_cast<float*>(smem_raw + 64 * 68 * 4);
    float* ssum = sW + 64 * 64;
    float* ssq  = ssum + 64;

    int tid = threadIdx.x;
    int rb  = blockIdx.x * 64;
    if (tid < 64) { ssum[tid] = 0.f; ssq[tid] = 0.f; }

    int tx = tid & 15, ty = tid >> 4;
    int c0 = tx * 4, r0 = ty * 4;

    // load z tile transposed + swizzled: row=channel k, col=node r
    for (int itr = 0; itr < 4; ++itr) {
        int r = ty + itr * 16;
        float4 v = make_float4(0.f, 0.f, 0.f, 0.f);
        if (rb + r < NN) v = *reinterpret_cast<const float4*>(g_z + (rb + r) * 64 + c0);
        int blk = r >> 2, w = r & 3;
        sA[(c0 + 0) * 68 + (swz(c0 + 0, blk) << 2) + w] = v.x;
        sA[(c0 + 1) * 68 + (swz(c0 + 1, blk) << 2) + w] = v.y;
        sA[(c0 + 2) * 68 + (swz(c0 + 2, blk) << 2) + w] = v.z;
        sA[(c0 + 3) * 68 + (swz(c0 + 3, blk) << 2) + w] = v.w;
    }
    for (int itr = 0; itr < 4; ++itr) {
        int idx = tid + itr * 256;
        reinterpret_cast<float4*>(sW)[idx] = __ldg(reinterpret_cast<const float4*>(W1) + idx);
    }
    __syncthreads();

    // ---- GEMM1: q[rp][c] pairs rows (r0,r0+1)/(r0+2,r0+3) against col c ----
    u64 q0 = 0, q1 = 0, q2 = 0, q3 = 0, q4 = 0, q5 = 0, q6 = 0, q7 = 0;
#pragma unroll 8
    for (int k = 0; k < 64; ++k) {
        ulonglong2 p = *reinterpret_cast<ulonglong2*>(&sA[k * 68 + (swz(k, ty) << 2)]);
        float4 wv    = *reinterpret_cast<float4*>(&sW[k * 64 + c0]);
        u64 ws0 = pk2(wv.x, wv.x), ws1 = pk2(wv.y, wv.y);
        u64 ws2 = pk2(wv.z, wv.z), ws3 = pk2(wv.w, wv.w);
        q0 = ffma2(p.x, ws0, q0); q1 = ffma2(p.x, ws1, q1);
        q2 = ffma2(p.x, ws2, q2); q3 = ffma2(p.x, ws3, q3);
        q4 = ffma2(p.y, ws0, q4); q5 = ffma2(p.y, ws1, q5);
        q6 = ffma2(p.y, ws2, q6); q7 = ffma2(p.y, ws3, q7);
    }
    float4 bb1 = __ldg(reinterpret_cast<const float4*>(b1 + c0));
    float tt[4][4];
    { float2 u = upk2(q0); tt[0][0] = u.x; tt[1][0] = u.y; }
    { float2 u = upk2(q1); tt[0][1] = u.x; tt[1][1] = u.y; }
    { float2 u = upk2(q2); tt[0][2] = u.x; tt[1][2] = u.y; }
    { float2 u = upk2(q3); tt[0][3] = u.x; tt[1][3] = u.y; }
    { float2 u = upk2(q4); tt[2][0] = u.x; tt[3][0] = u.y; }
    { float2 u = upk2(q5); tt[2][1] = u.x; tt[3][1] = u.y; }
    { float2 u = upk2(q6); tt[2][2] = u.x; tt[3][2] = u.y; }
    { float2 u = upk2(q7); tt[2][3] = u.x; tt[3][3] = u.y; }
#pragma unroll
    for (int i = 0; i < 4; ++i) {
        tt[i][0] = fmaxf(tt[i][0] + bb1.x, 0.f);
        tt[i][1] = fmaxf(tt[i][1] + bb1.y, 0.f);
        tt[i][2] = fmaxf(tt[i][2] + bb1.z, 0.f);
        tt[i][3] = fmaxf(tt[i][3] + bb1.w, 0.f);
    }
    __syncthreads();  // everyone done reading sA / sW

    // store t transposed + swizzled (row = channel c0+j, col = node r0+i)
#pragma unroll
    for (int j = 0; j < 4; ++j) {
        int sb = swz(c0 + j, ty) << 2;   // (r0+i)>>2 == ty for i<4
#pragma unroll
        for (int i = 0; i < 4; ++i)
            sA[(c0 + j) * 68 + sb + i] = tt[i][j];
    }
    for (int itr = 0; itr < 4; ++itr) {
        int idx = tid + itr * 256;
        reinterpret_cast<float4*>(sW)[idx] = __ldg(reinterpret_cast<const float4*>(W2) + idx);
    }
    __syncthreads();

    // ---- GEMM2 ----
    q0 = q1 = q2 = q3 = q4 = q5 = q6 = q7 = 0;
#pragma unroll 8
    for (int k = 0; k < 64; ++k) {
        ulonglong2 p = *reinterpret_cast<ulonglong2*>(&sA[k * 68 + (swz(k, ty) << 2)]);
        float4 wv    = *reinterpret_cast<float4*>(&sW[k * 64 + c0]);
        u64 ws0 = pk2(wv.x, wv.x), ws1 = pk2(wv.y, wv.y);
        u64 ws2 = pk2(wv.z, wv.z), ws3 = pk2(wv.w, wv.w);
        q0 = ffma2(p.x, ws0, q0); q1 = ffma2(p.x, ws1, q1);
        q2 = ffma2(p.x, ws2, q2); q3 = ffma2(p.x, ws3, q3);
        q4 = ffma2(p.y, ws0, q4); q5 = ffma2(p.y, ws1, q5);
        q6 = ffma2(p.y, ws2, q6); q7 = ffma2(p.y, ws3, q7);
    }
    float4 bb2 = __ldg(reinterpret_cast<const float4*>(b2 + c0));
    float yy[4][4];
    { float2 u = upk2(q0); yy[0][0] = u.x + bb2.x; yy[1][0] = u.y + bb2.x; }
    { float2 u = upk2(q1); yy[0][1] = u.x + bb2.y; yy[1][1] = u.y + bb2.y; }
    { float2 u = upk2(q2); yy[0][2] = u.x + bb2.z; yy[1][2] = u.y + bb2.z; }
    { float2 u = upk2(q3); yy[0][3] = u.x + bb2.w; yy[1][3] = u.y + bb2.w; }
    { float2 u = upk2(q4); yy[2][0] = u.x + bb2.x; yy[3][0] = u.y + bb2.x; }
    { float2 u = upk2(q5); yy[2][1] = u.x + bb2.y; yy[3][1] = u.y + bb2.y; }
    { float2 u = upk2(q6); yy[2][2] = u.x + bb2.z; yy[3][2] = u.y + bb2.z; }
    { float2 u = upk2(q7); yy[2][3] = u.x + bb2.w; yy[3][3] = u.y + bb2.w; }

    // write y + accumulate stats
#pragma unroll
    for (int i = 0; i < 4; ++i) {
        int r = rb + r0 + i;
        if (r < NN) {
            float4 v = make_float4(yy[i][0], yy[i][1], yy[i][2], yy[i][3]);
            *reinterpret_cast<float4*>(g_y + r * 64 + c0) = v;
        }
    }
#pragma unroll
    for (int j = 0; j < 4; ++j) {
        float sj = 0.f, qj = 0.f;
#pragma unroll
        for (int i = 0; i < 4; ++i) {
            if (rb + r0 + i < NN) { sj += yy[i][j]; qj += yy[i][j] * yy[i][j]; }
        }
        atomicAdd(&ssum[c0 + j], sj);
        atomicAdd(&ssq[c0 + j], qj);
    }
    __syncthreads();
    if (tid < 64) {
        atomicAdd(&g_stats[tid], ssum[tid]);
        atomicAdd(&g_stats[64 + tid], ssq[tid]);
    }
}

// K4: BN finalize (per-block redundant) + h = relu(y*scale+shift) + h
__global__ void k4_post(const float* __restrict__ gamma, const float* __restrict__ beta,
                        float* __restrict__ out_final, int last) {
    __shared__ float s_sc[HD], s_sh[HD];
    int tid = threadIdx.x;
    if (tid < HD) {
        float mean = g_stats[tid] * (1.f / NN);
        float var  = g_stats[HD + tid] * (1.f / NN) - mean * mean;
        float inv  = rsqrtf(var + BN_EPS);
        float sc   = gamma[tid] * inv;
        s_sc[tid] = sc;
        s_sh[tid] = beta[tid] - mean * sc;
    }
    __syncthreads();
    int i = blockIdx.x * blockDim.x + tid;
    if (i >= NN * (HD / 4)) return;
    int c0 = (i & 15) * 4;
    float4 y  = reinterpret_cast<const float4*>(g_y)[i];
    float4 h  = reinterpret_cast<const float4*>(g_h)[i];
    float4 sc = *reinterpret_cast<const float4*>(&s_sc[c0]);
    float4 sh = *reinterpret_cast<const float4*>(&s_sh[c0]);
    float4 o;
    o.x = fmaxf(fmaf(y.x, sc.x, sh.x), 0.f) + h.x;
    o.y = fmaxf(fmaf(y.y, sc.y, sh.y), 0.f) + h.y;
    o.z = fmaxf(fmaf(y.z, sc.z, sh.z), 0.f) + h.z;
    o.w = fmaxf(fmaf(y.w, sc.w, sh.w), 0.f) + h.w;
    float4* dst = last ? reinterpret_cast<float4*>(out_final)
                       : reinterpret_cast<float4*>(g_h);
    dst[i] = o;
}

// ---------------- launch ----------------------------------------------------

extern "C" void kernel_launch(void* const* d_in, const int* in_sizes, int n_in,
                              void* d_out, int out_size) {
    const float* node_feat = (const float*)d_in[0];
    const float* edge_feat = (const float*)d_in[1];
    const int*   src       = (const int*)d_in[2];
    const int*   dst       = (const int*)d_in[3];
    const float* We        = (const float*)d_in[4];
    const float* be        = (const float*)d_in[5];
    const float* W1        = (const float*)d_in[6];
    const float* b1        = (const float*)d_in[7];
    const float* W2        = (const float*)d_in[8];
    const float* b2        = (const float*)d_in[9];
    const float* gamma     = (const float*)d_in[10];
    const float* beta      = (const float*)d_in[11];
    float* out = (float*)d_out;

    cudaFuncSetAttribute(k2_mlp, cudaFuncAttributeMaxDynamicSharedMemorySize, K2_SMEM);

    const int T = 256;
    k_slot<<<1, 32>>>();   // shifts capture slot: launch #4 = k_scatter
    k_hist<<<(NE + T - 1) / T, T>>>(dst);
    k_scan1<<<NCHUNKS, 512>>>();
    k_scatter<<<(NE + T - 1) / T, T>>>(src, dst,
                                       reinterpret_cast<const float4*>(edge_feat),
                                       reinterpret_cast<const float4*>(node_feat));

    for (int l = 0; l < 4; ++l) {
        k1_gather<<<NN / 2, 64>>>(We, be);
        k2_mlp<<<(NN + 63) / 64, 256, K2_SMEM>>>(W1 + l * HD * HD, b1 + l * HD,
                                                 W2 + l * HD * HD, b2 + l * HD);
        k4_post<<<(NN * 16 + T - 1) / T, T>>>(gamma + l * HD, beta + l * HD,
                                              out, l == 3 ? 1 : 0);
    }
}